// round 11
// baseline (speedup 1.0000x reference)
#include <cuda_runtime.h>
#include <cuda_fp16.h>
#include <cstdint>

#define BATCH 2
#define SEQ 2048
#define DIM 1024
#define HEADS 16
#define DHEAD 64
#define BS (BATCH*SEQ)   // 4096

// ---------------- scratch (device globals; no allocations allowed) ----------
__device__ __half g_tokh[BS*DIM], g_tokl[BS*DIM];
__device__ __half g_qh[BS*DIM], g_ql[BS*DIM];
__device__ __half g_kh[BS*DIM], g_kl[BS*DIM];
__device__ __half g_vh[BS*DIM], g_vl[BS*DIM];
__device__ __half g_aggh[BS*DIM], g_aggl[BS*DIM];
__device__ __half g_wqh[DIM*DIM], g_wql[DIM*DIM];
__device__ __half g_wkh[DIM*DIM], g_wkl[DIM*DIM];
__device__ __half g_wvh[DIM*DIM], g_wvl[DIM*DIM];
__device__ __half g_woh[DIM*DIM], g_wol[DIM*DIM];

// ---------------- helpers ----------------------------------------------------
__device__ __forceinline__ uint32_t smem_u32(const void* p) {
    uint32_t a;
    asm("{ .reg .u64 t; cvta.to.shared.u64 t, %1; cvt.u32.u64 %0, t; }"
        : "=r"(a) : "l"(p));
    return a;
}
#define SWZ128(o) ((o) ^ (((o) >> 3) & 0x70))

__device__ __forceinline__ void cp16(uint32_t saddr, const void* gptr) {
    asm volatile("cp.async.cg.shared.global [%0], [%1], 16;"
                 :: "r"(saddr), "l"(gptr));
}
#define CP_COMMIT() asm volatile("cp.async.commit_group;" ::: "memory")
#define CP_WAIT0()  asm volatile("cp.async.wait_group 0;" ::: "memory")

__device__ __forceinline__ void ldsm_x4(uint32_t* r, uint32_t addr) {
    asm volatile("ldmatrix.sync.aligned.m8n8.x4.shared.b16 {%0,%1,%2,%3}, [%4];"
                 : "=r"(r[0]), "=r"(r[1]), "=r"(r[2]), "=r"(r[3]) : "r"(addr));
}
__device__ __forceinline__ void ldsm_x2(uint32_t* r, uint32_t addr) {
    asm volatile("ldmatrix.sync.aligned.m8n8.x2.shared.b16 {%0,%1}, [%2];"
                 : "=r"(r[0]), "=r"(r[1]) : "r"(addr));
}
__device__ __forceinline__ void ldsm_x4t(uint32_t* r, uint32_t addr) {
    asm volatile("ldmatrix.sync.aligned.m8n8.x4.trans.shared.b16 {%0,%1,%2,%3}, [%4];"
                 : "=r"(r[0]), "=r"(r[1]), "=r"(r[2]), "=r"(r[3]) : "r"(addr));
}
__device__ __forceinline__ void mma_f16(float* c, const uint32_t* a, const uint32_t* b) {
    asm volatile(
        "mma.sync.aligned.m16n8k16.row.col.f32.f16.f16.f32 "
        "{%0,%1,%2,%3}, {%4,%5,%6,%7}, {%8,%9}, {%0,%1,%2,%3};"
        : "+f"(c[0]), "+f"(c[1]), "+f"(c[2]), "+f"(c[3])
        : "r"(a[0]), "r"(a[1]), "r"(a[2]), "r"(a[3]), "r"(b[0]), "r"(b[1]));
}
__device__ __forceinline__ float ex2(float x) {
    float y;
    asm("ex2.approx.ftz.f32 %0, %1;" : "=f"(y) : "f"(x));
    return y;
}
__device__ __forceinline__ void hsplit(float v, __half& h, __half& l) {
    h = __float2half_rn(v);
    l = __float2half_rn(v - __half2float(h));
}
__device__ __forceinline__ void hsplit2(float a, float b, uint32_t& hi, uint32_t& lo) {
    __half2 h = __floats2half2_rn(a, b);
    float2 f = __half22float2(h);
    __half2 l = __floats2half2_rn(a - f.x, b - f.y);
    hi = *reinterpret_cast<uint32_t*>(&h);
    lo = *reinterpret_cast<uint32_t*>(&l);
}

// ---------------- fused split + pack kernel ----------------------------------
// blocks [0, 4096): split tokens (1M float4); blocks [4096, 8192): pack weights
#define QSCALE 0.18033688011112042f   // 0.125 * log2(e)

__global__ void prep_all(const float4* __restrict__ tok,
                         const float* __restrict__ wq, const float* __restrict__ wk,
                         const float* __restrict__ wv, const float* __restrict__ wo) {
    int blk = blockIdx.x;
    if (blk < 4096) {
        int i = blk * 256 + threadIdx.x;          // < 1048576 = BS*DIM/4
        float4 v = tok[i];
        uint32_t h01, l01, h23, l23;
        hsplit2(v.x, v.y, h01, l01);
        hsplit2(v.z, v.w, h23, l23);
        uint32_t* H = reinterpret_cast<uint32_t*>(g_tokh);
        uint32_t* L = reinterpret_cast<uint32_t*>(g_tokl);
        H[2 * i] = h01; H[2 * i + 1] = h23;
        L[2 * i] = l01; L[2 * i + 1] = l23;
    } else {
        int idx = (blk - 4096) * 256 + threadIdx.x;   // < 1048576 = DIM*DIM
        int n = idx >> 10;
        int k = idx & 1023;
        int h = n >> 6, e = n & 63;
        int src = (h * DIM + k) * DHEAD + e;
        hsplit(wq[src] * QSCALE, g_wqh[idx], g_wql[idx]);
        hsplit(wk[src], g_wkh[idx], g_wkl[idx]);
        hsplit(wv[src], g_wvh[idx], g_wvl[idx]);
        hsplit(wo[k * DIM + n], g_woh[idx], g_wol[idx]);
    }
}

// ---------------- fp16x3 GEMM (HMMA + cp.async 2-stage) -----------------------
#define ST_AL 16384
#define ST_BH 32768
#define ST_BL 40960
#define ST_SZ 49152
#define GS2_TOTAL (2*ST_SZ)

template <bool SPLIT>
__device__ __forceinline__ void gemm_body(
    const __half* __restrict__ Ah, const __half* __restrict__ Al,
    const __half* __restrict__ Bh, const __half* __restrict__ Bl,
    float* __restrict__ C, __half* __restrict__ Ch,
    __half* __restrict__ Cl, char* smem) {
    const uint32_t sb = smem_u32(smem);
    const int tid = threadIdx.x;
    const int lane = tid & 31;
    const int wid = tid >> 5;
    const int warp_m = wid & 3;
    const int warp_n = wid >> 2;
    const int row0 = blockIdx.y * 128;
    const int col0 = blockIdx.x * 64;

    const uint4* gA[2] = {reinterpret_cast<const uint4*>(Ah + (size_t)row0 * DIM),
                          reinterpret_cast<const uint4*>(Al + (size_t)row0 * DIM)};
    const uint4* gB[2] = {reinterpret_cast<const uint4*>(Bh + (size_t)col0 * DIM),
                          reinterpret_cast<const uint4*>(Bl + (size_t)col0 * DIM)};

    const int lrow = tid >> 3, lcol = tid & 7;

    auto load_stage = [&](int cidx, int s) {
        const int k0u = cidx * 8;
        const uint32_t sbase = sb + s * ST_SZ;
#pragma unroll
        for (int m = 0; m < 2; m++) {
#pragma unroll
            for (int r4 = 0; r4 < 4; r4++) {
                int row = lrow + r4 * 32;
                uint32_t off = SWZ128(row * 128 + lcol * 16);
                cp16(sbase + (m ? ST_AL : 0) + off, gA[m] + row * 128 + k0u + lcol);
            }
#pragma unroll
            for (int r4 = 0; r4 < 2; r4++) {
                int row = lrow + r4 * 32;
                uint32_t off = SWZ128(row * 128 + lcol * 16);
                cp16(sbase + (m ? ST_BL : ST_BH) + off, gB[m] + row * 128 + k0u + lcol);
            }
        }
        CP_COMMIT();
    };

    int amask[2], abase[2];
#pragma unroll
    for (int i = 0; i < 2; i++) {
        int r = warp_m * 32 + i * 16 + (lane & 15);
        amask[i] = (r & 7) << 4;
        abase[i] = r * 128 + ((lane >> 4) & 1) * 16;
    }
    const int brow = warp_n * 32 + (lane & 7);
    const int bmaskbase = ((lane & 15) >> 3) * 16;

    float acc[2][4][4] = {};

    load_stage(0, 0);
    CP_WAIT0();
    __syncthreads();

    for (int c = 0; c < 16; c++) {
        if (c < 15) load_stage(c + 1, (c + 1) & 1);
        const uint32_t sbase = sb + (c & 1) * ST_SZ;
#pragma unroll
        for (int ks = 0; ks < 4; ks++) {
            uint32_t ah[2][4], al[2][4], bh[4][2], bl[4][2];
#pragma unroll
            for (int i = 0; i < 2; i++) {
                uint32_t offA = (abase[i] + ks * 32) ^ amask[i];
                ldsm_x4(ah[i], sbase + offA);
                ldsm_x4(al[i], sbase + ST_AL + offA);
            }
#pragma unroll
            for (int j = 0; j < 4; j++) {
                int r = brow + j * 8;
                uint32_t offB = (r * 128 + bmaskbase + ks * 32) ^ ((r & 7) << 4);
                ldsm_x2(bh[j], sbase + ST_BH + offB);
                ldsm_x2(bl[j], sbase + ST_BL + offB);
            }
#pragma unroll
            for (int i = 0; i < 2; i++)
#pragma unroll
                for (int j = 0; j < 4; j++)
                    mma_f16(acc[i][j], ah[i], bh[j]);
#pragma unroll
            for (int i = 0; i < 2; i++)
#pragma unroll
                for (int j = 0; j < 4; j++)
                    mma_f16(acc[i][j], ah[i], bl[j]);
#pragma unroll
            for (int i = 0; i < 2; i++)
#pragma unroll
                for (int j = 0; j < 4; j++)
                    mma_f16(acc[i][j], al[i], bh[j]);
        }
        if (c < 15) {
            CP_WAIT0();
            __syncthreads();
        }
    }

    const int fr = lane >> 2, fc = (lane & 3) * 2;
#pragma unroll
    for (int i = 0; i < 2; i++) {
        int rbase = row0 + warp_m * 32 + i * 16 + fr;
#pragma unroll
        for (int j = 0; j < 4; j++) {
            int col = col0 + warp_n * 32 + j * 8 + fc;
            if (SPLIT) {
                uint32_t h01, l01;
                hsplit2(acc[i][j][0], acc[i][j][1], h01, l01);
                *reinterpret_cast<uint32_t*>(&Ch[(size_t)rbase * DIM + col]) = h01;
                *reinterpret_cast<uint32_t*>(&Cl[(size_t)rbase * DIM + col]) = l01;
                hsplit2(acc[i][j][2], acc[i][j][3], h01, l01);
                *reinterpret_cast<uint32_t*>(&Ch[(size_t)(rbase + 8) * DIM + col]) = h01;
                *reinterpret_cast<uint32_t*>(&Cl[(size_t)(rbase + 8) * DIM + col]) = l01;
            } else {
                *reinterpret_cast<float2*>(&C[(size_t)rbase * DIM + col]) =
                    make_float2(acc[i][j][0], acc[i][j][1]);
                *reinterpret_cast<float2*>(&C[(size_t)(rbase + 8) * DIM + col]) =
                    make_float2(acc[i][j][2], acc[i][j][3]);
            }
        }
    }
}

struct QKVArgs {
    const __half* bh[3];
    const __half* bl[3];
    __half* ch[3];
    __half* cl[3];
};

__global__ __launch_bounds__(256, 2) void gemm_qkv(
    const __half* __restrict__ Ah, const __half* __restrict__ Al,
    QKVArgs args) {
    extern __shared__ char smem[];
    const int z = blockIdx.z;
    gemm_body<true>(Ah, Al, args.bh[z], args.bl[z], nullptr,
                    args.ch[z], args.cl[z], smem);
}

__global__ __launch_bounds__(256, 2) void gemm_wo(
    const __half* __restrict__ Ah, const __half* __restrict__ Al,
    const __half* __restrict__ Bh, const __half* __restrict__ Bl,
    float* __restrict__ C) {
    extern __shared__ char smem[];
    gemm_body<false>(Ah, Al, Bh, Bl, C, nullptr, nullptr, smem);
}

// ---------------- flash attention (fp16; QK x3 exp2 domain, PV x1) -----------
// Q fragments hoisted to registers (invariant across KV loop).
#define FA_QL 16384
#define FA_KV0 32768
#define FA_KVS 24576
#define FA_KL_O 8192
#define FA_VH_O 16384
#define FA_TOTAL (32768 + 2*24576)   // 81920

__global__ __launch_bounds__(256, 2) void flash_attn_mma(
    const __half* __restrict__ Qh, const __half* __restrict__ Ql,
    const __half* __restrict__ Kh, const __half* __restrict__ Kl,
    const __half* __restrict__ Vh,
    __half* __restrict__ Oh, __half* __restrict__ Ol) {
    extern __shared__ char smem[];
    const uint32_t sb = smem_u32(smem);
    const int tid = threadIdx.x, lane = tid & 31, wid = tid >> 5;
    const int qt = blockIdx.x, bhid = blockIdx.y;
    const int b = bhid >> 4, h = bhid & 15;
    const size_t base = ((size_t)(b * SEQ) * HEADS + h) * DHEAD;
    const uint4* Qhp = reinterpret_cast<const uint4*>(Qh + base);
    const uint4* Qlp = reinterpret_cast<const uint4*>(Ql + base);
    const uint4* Khp = reinterpret_cast<const uint4*>(Kh + base);
    const uint4* Klp = reinterpret_cast<const uint4*>(Kl + base);
    const uint4* Vhp = reinterpret_cast<const uint4*>(Vh + base);

    const int lrw = tid >> 3, lcl = tid & 7;

    auto load_kv = [&](int jt, int s) {
        const uint32_t kvb = sb + FA_KV0 + s * FA_KVS;
#pragma unroll
        for (int r4 = 0; r4 < 2; r4++) {
            int row = lrw + r4 * 32;
            uint32_t off = SWZ128(row * 128 + lcl * 16);
            int g = (jt * 64 + row) * 128 + lcl;
            cp16(kvb + off, Khp + g);
            cp16(kvb + FA_KL_O + off, Klp + g);
            cp16(kvb + FA_VH_O + off, Vhp + g);
        }
        CP_COMMIT();
    };

    load_kv(0, 0);
#pragma unroll
    for (int r4 = 0; r4 < 4; r4++) {
        int row = lrw + r4 * 32;
        uint32_t off = SWZ128(row * 128 + lcl * 16);
        int g = (qt * 128 + row) * 128 + lcl;
        *reinterpret_cast<uint4*>(smem + off) = Qhp[g];
        *reinterpret_cast<uint4*>(smem + FA_QL + off) = Qlp[g];
    }

    float m0 = -1e30f, m1 = -1e30f, l0 = 0.f, l1 = 0.f;
    float o[8][4] = {};
    const int fr = lane >> 2, fc = (lane & 3) * 2;
    const int qrow = wid * 16;
    const int aRow = lane & 15, aCol = (lane >> 4) * 16;
    const int kRow = ((lane >> 4) & 1) * 8 + (lane & 7);
    const int kHalf = ((lane >> 3) & 1) * 16;
    const int vRow = lane & 15;
    const int vColOff = ((lane >> 4) & 1) * 8;

    CP_WAIT0();
    __syncthreads();

    // hoist Q fragments (invariant across all KV iterations)
    uint32_t qfh[4][4], qfl[4][4];
#pragma unroll
    for (int ks = 0; ks < 4; ks++) {
        uint32_t offA = SWZ128((qrow + aRow) * 128 + ks * 32 + aCol);
        ldsm_x4(qfh[ks], sb + offA);
        ldsm_x4(qfl[ks], sb + FA_QL + offA);
    }

    for (int jt = 0; jt < SEQ / 64; jt++) {
        const uint32_t kvb = sb + FA_KV0 + (jt & 1) * FA_KVS;
        if (jt + 1 < SEQ / 64) load_kv(jt + 1, (jt + 1) & 1);

        // ---- S = Q K^T (fp16 x3), exp2 domain ----
        float s[8][4] = {};
#pragma unroll
        for (int ks = 0; ks < 4; ks++) {
#pragma unroll
            for (int jp = 0; jp < 2; jp++) {
                uint32_t kh4[2][4], kl4[2][4];
#pragma unroll
                for (int u = 0; u < 2; u++) {
                    int jj = jp * 2 + u;
                    uint32_t offB = SWZ128((jj * 16 + kRow) * 128 + ks * 32 + kHalf);
                    ldsm_x4(kh4[u], kvb + offB);
                    ldsm_x4(kl4[u], kvb + FA_KL_O + offB);
                }
#pragma unroll
                for (int u = 0; u < 2; u++) {
                    int jj = jp * 2 + u;
                    mma_f16(s[2 * jj], qfh[ks], kh4[u]);
                    mma_f16(s[2 * jj + 1], qfh[ks], kh4[u] + 2);
                }
#pragma unroll
                for (int u = 0; u < 2; u++) {
                    int jj = jp * 2 + u;
                    mma_f16(s[2 * jj], qfh[ks], kl4[u]);
                    mma_f16(s[2 * jj + 1], qfh[ks], kl4[u] + 2);
                }
#pragma unroll
                for (int u = 0; u < 2; u++) {
                    int jj = jp * 2 + u;
                    mma_f16(s[2 * jj], qfl[ks], kh4[u]);
                    mma_f16(s[2 * jj + 1], qfl[ks], kh4[u] + 2);
                }
            }
        }

        // ---- warp-local row max ----
        float rm0 = s[0][0], rm1 = s[0][2];
#pragma unroll
        for (int j = 0; j < 8; j++) {
            rm0 = fmaxf(rm0, fmaxf(s[j][0], s[j][1]));
            rm1 = fmaxf(rm1, fmaxf(s[j][2], s[j][3]));
        }
        rm0 = fmaxf(rm0, __shfl_xor_sync(0xffffffffu, rm0, 1));
        rm0 = fmaxf(rm0, __shfl_xor_sync(0xffffffffu, rm0, 2));
        rm1 = fmaxf(rm1, __shfl_xor_sync(0xffffffffu, rm1, 1));
        rm1 = fmaxf(rm1, __shfl_xor_sync(0xffffffffu, rm1, 2));
        float mn0 = fmaxf(m0, rm0), mn1 = fmaxf(m1, rm1);
        float a0 = ex2(m0 - mn0), a1 = ex2(m1 - mn1);
        m0 = mn0; m1 = mn1;

#pragma unroll
        for (int j = 0; j < 8; j++) {
            o[j][0] *= a0; o[j][1] *= a0;
            o[j][2] *= a1; o[j][3] *= a1;
        }

        // ---- PV x1 with fused exp2/pack ----
        float rs0 = 0.f, rs1 = 0.f;
#pragma unroll
        for (int kt = 0; kt < 4; kt++) {
            uint32_t pA[4];
#pragma unroll
            for (int u = 0; u < 2; u++) {
                int j = 2 * kt + u;
                float p0 = ex2(s[j][0] - mn0);
                float p1 = ex2(s[j][1] - mn0);
                float p2 = ex2(s[j][2] - mn1);
                float p3 = ex2(s[j][3] - mn1);
                rs0 += p0 + p1; rs1 += p2 + p3;
                __half2 t01 = __floats2half2_rn(p0, p1);
                __half2 t23 = __floats2half2_rn(p2, p3);
                pA[2 * u] = *reinterpret_cast<uint32_t*>(&t01);
                pA[2 * u + 1] = *reinterpret_cast<uint32_t*>(&t23);
            }
#pragma unroll
            for (int jj = 0; jj < 4; jj++) {
                uint32_t vh4[4];
                uint32_t offV = SWZ128((kt * 16 + vRow) * 128 + (jj * 16 + vColOff) * 2);
                ldsm_x4t(vh4, kvb + FA_VH_O + offV);
                mma_f16(o[2 * jj], pA, vh4);
                mma_f16(o[2 * jj + 1], pA, vh4 + 2);
            }
        }
        rs0 += __shfl_xor_sync(0xffffffffu, rs0, 1);
        rs0 += __shfl_xor_sync(0xffffffffu, rs0, 2);
        rs1 += __shfl_xor_sync(0xffffffffu, rs1, 1);
        rs1 += __shfl_xor_sync(0xffffffffu, rs1, 2);
        l0 = l0 * a0 + rs0;
        l1 = l1 * a1 + rs1;

        if (jt + 1 < SEQ / 64) CP_WAIT0();
        __syncthreads();
    }

    // ---- epilogue: normalize, split, store [b,n,h,e] ----
    float inv0 = 1.f / l0, inv1 = 1.f / l1;
    const int r0g = qt * 128 + qrow + fr;
#pragma unroll
    for (int j = 0; j < 8; j++) {
        int col = j * 8 + fc;
        uint32_t h01, l01;
        hsplit2(o[j][0] * inv0, o[j][1] * inv0, h01, l01);
        *reinterpret_cast<uint32_t*>(Oh + base + (size_t)r0g * 1024 + col) = h01;
        *reinterpret_cast<uint32_t*>(Ol + base + (size_t)r0g * 1024 + col) = l01;
        hsplit2(o[j][2] * inv1, o[j][3] * inv1, h01, l01);
        *reinterpret_cast<uint32_t*>(Oh + base + (size_t)(r0g + 8) * 1024 + col) = h01;
        *reinterpret_cast<uint32_t*>(Ol + base + (size_t)(r0g + 8) * 1024 + col) = l01;
    }
}

// ---------------- launch ------------------------------------------------------
extern "C" void kernel_launch(void* const* d_in, const int* in_sizes, int n_in,
                              void* d_out, int out_size) {
    const float* tokens = (const float*)d_in[0];
    const float* wq = (const float*)d_in[1];
    const float* wk = (const float*)d_in[2];
    const float* wv = (const float*)d_in[3];
    const float* wo = (const float*)d_in[4];
    float* out = (float*)d_out;

    __half *tokh, *tokl, *qh, *ql, *kh, *kl, *vh, *vl, *aggh, *aggl;
    __half *wqh, *wql, *wkh, *wkl, *wvh, *wvl, *woh, *wol;
    cudaGetSymbolAddress((void**)&tokh, g_tokh);
    cudaGetSymbolAddress((void**)&tokl, g_tokl);
    cudaGetSymbolAddress((void**)&qh, g_qh);
    cudaGetSymbolAddress((void**)&ql, g_ql);
    cudaGetSymbolAddress((void**)&kh, g_kh);
    cudaGetSymbolAddress((void**)&kl, g_kl);
    cudaGetSymbolAddress((void**)&vh, g_vh);
    cudaGetSymbolAddress((void**)&vl, g_vl);
    cudaGetSymbolAddress((void**)&aggh, g_aggh);
    cudaGetSymbolAddress((void**)&aggl, g_aggl);
    cudaGetSymbolAddress((void**)&wqh, g_wqh);
    cudaGetSymbolAddress((void**)&wql, g_wql);
    cudaGetSymbolAddress((void**)&wkh, g_wkh);
    cudaGetSymbolAddress((void**)&wkl, g_wkl);
    cudaGetSymbolAddress((void**)&wvh, g_wvh);
    cudaGetSymbolAddress((void**)&wvl, g_wvl);
    cudaGetSymbolAddress((void**)&woh, g_woh);
    cudaGetSymbolAddress((void**)&wol, g_wol);

    prep_all<<<8192, 256>>>((const float4*)tokens, wq, wk, wv, wo);

    cudaFuncSetAttribute(gemm_qkv, cudaFuncAttributeMaxDynamicSharedMemorySize,
                         GS2_TOTAL);
    cudaFuncSetAttribute(gemm_wo, cudaFuncAttributeMaxDynamicSharedMemorySize,
                         GS2_TOTAL);

    QKVArgs args;
    args.bh[0] = wqh; args.bl[0] = wql; args.ch[0] = qh; args.cl[0] = ql;
    args.bh[1] = wkh; args.bl[1] = wkl; args.ch[1] = kh; args.cl[1] = kl;
    args.bh[2] = wvh; args.bl[2] = wvl; args.ch[2] = vh; args.cl[2] = vl;

    dim3 gqkv(DIM / 64, BS / 128, 3);
    gemm_qkv<<<gqkv, 256, GS2_TOTAL>>>(tokh, tokl, args);

    cudaFuncSetAttribute(flash_attn_mma,
                         cudaFuncAttributeMaxDynamicSharedMemorySize, FA_TOTAL);
    flash_attn_mma<<<dim3(SEQ / 128, BATCH * HEADS), 256, FA_TOTAL>>>(
        qh, ql, kh, kl, vh, aggh, aggl);

    dim3 gp(DIM / 64, BS / 128);
    gemm_wo<<<gp, 256, GS2_TOTAL>>>(aggh, aggl, woh, wol, out);
}

// round 12
// speedup vs baseline: 1.0357x; 1.0357x over previous
#include <cuda_runtime.h>
#include <cuda_fp16.h>
#include <cstdint>

#define BATCH 2
#define SEQ 2048
#define DIM 1024
#define HEADS 16
#define DHEAD 64
#define BS (BATCH*SEQ)   // 4096

// ---------------- scratch (device globals; no allocations allowed) ----------
__device__ __half g_tokh[BS*DIM], g_tokl[BS*DIM];
__device__ __half g_qh[BS*DIM], g_ql[BS*DIM];
__device__ __half g_kh[BS*DIM], g_kl[BS*DIM];
__device__ __half g_vh[BS*DIM], g_vl[BS*DIM];
__device__ __half g_aggh[BS*DIM], g_aggl[BS*DIM];
__device__ __half g_wqh[DIM*DIM], g_wql[DIM*DIM];
__device__ __half g_wkh[DIM*DIM], g_wkl[DIM*DIM];
__device__ __half g_wvh[DIM*DIM], g_wvl[DIM*DIM];
__device__ __half g_woh[DIM*DIM], g_wol[DIM*DIM];

// ---------------- helpers ----------------------------------------------------
__device__ __forceinline__ uint32_t smem_u32(const void* p) {
    uint32_t a;
    asm("{ .reg .u64 t; cvta.to.shared.u64 t, %1; cvt.u32.u64 %0, t; }"
        : "=r"(a) : "l"(p));
    return a;
}
#define SWZ128(o) ((o) ^ (((o) >> 3) & 0x70))

__device__ __forceinline__ void cp16(uint32_t saddr, const void* gptr) {
    asm volatile("cp.async.cg.shared.global [%0], [%1], 16;"
                 :: "r"(saddr), "l"(gptr));
}
#define CP_COMMIT() asm volatile("cp.async.commit_group;" ::: "memory")
#define CP_WAIT0()  asm volatile("cp.async.wait_group 0;" ::: "memory")

__device__ __forceinline__ void ldsm_x4(uint32_t* r, uint32_t addr) {
    asm volatile("ldmatrix.sync.aligned.m8n8.x4.shared.b16 {%0,%1,%2,%3}, [%4];"
                 : "=r"(r[0]), "=r"(r[1]), "=r"(r[2]), "=r"(r[3]) : "r"(addr));
}
__device__ __forceinline__ void ldsm_x2(uint32_t* r, uint32_t addr) {
    asm volatile("ldmatrix.sync.aligned.m8n8.x2.shared.b16 {%0,%1}, [%2];"
                 : "=r"(r[0]), "=r"(r[1]) : "r"(addr));
}
__device__ __forceinline__ void ldsm_x4t(uint32_t* r, uint32_t addr) {
    asm volatile("ldmatrix.sync.aligned.m8n8.x4.trans.shared.b16 {%0,%1,%2,%3}, [%4];"
                 : "=r"(r[0]), "=r"(r[1]), "=r"(r[2]), "=r"(r[3]) : "r"(addr));
}
__device__ __forceinline__ void mma_f16(float* c, const uint32_t* a, const uint32_t* b) {
    asm volatile(
        "mma.sync.aligned.m16n8k16.row.col.f32.f16.f16.f32 "
        "{%0,%1,%2,%3}, {%4,%5,%6,%7}, {%8,%9}, {%0,%1,%2,%3};"
        : "+f"(c[0]), "+f"(c[1]), "+f"(c[2]), "+f"(c[3])
        : "r"(a[0]), "r"(a[1]), "r"(a[2]), "r"(a[3]), "r"(b[0]), "r"(b[1]));
}
__device__ __forceinline__ float ex2(float x) {
    float y;
    asm("ex2.approx.ftz.f32 %0, %1;" : "=f"(y) : "f"(x));
    return y;
}
__device__ __forceinline__ void hsplit(float v, __half& h, __half& l) {
    h = __float2half_rn(v);
    l = __float2half_rn(v - __half2float(h));
}
__device__ __forceinline__ void hsplit2(float a, float b, uint32_t& hi, uint32_t& lo) {
    __half2 h = __floats2half2_rn(a, b);
    float2 f = __half22float2(h);
    __half2 l = __floats2half2_rn(a - f.x, b - f.y);
    hi = *reinterpret_cast<uint32_t*>(&h);
    lo = *reinterpret_cast<uint32_t*>(&l);
}

// ---------------- fused prep: token split + coalesced weight transpose ------
// blocks [0, 4096): split tokens (1M float4)
// blocks [4096, 8192): 32x32-tile transposes of wq/wk/wv (per-head) and wo
#define QSCALE 0.18033688011112042f   // 0.125 * log2(e)

__global__ void prep_all(const float4* __restrict__ tok,
                         const float* __restrict__ wq, const float* __restrict__ wk,
                         const float* __restrict__ wv, const float* __restrict__ wo) {
    __shared__ float tile[32][33];
    const int blk = blockIdx.x;
    const int tid = threadIdx.x;

    if (blk < 4096) {
        int i = blk * 256 + tid;          // < 1048576 = BS*DIM/4
        float4 v = tok[i];
        uint32_t h01, l01, h23, l23;
        hsplit2(v.x, v.y, h01, l01);
        hsplit2(v.z, v.w, h23, l23);
        uint32_t* H = reinterpret_cast<uint32_t*>(g_tokh);
        uint32_t* L = reinterpret_cast<uint32_t*>(g_tokl);
        H[2 * i] = h01; H[2 * i + 1] = h23;
        L[2 * i] = l01; L[2 * i + 1] = l23;
        return;
    }

    const int wb = blk - 4096;            // [0, 4096)
    if (wb < 3072) {
        // qkv: per-head transpose [1024 d][64 e] -> dst[n = h*64+e][k = d]
        const int arr = wb >> 10;         // 0=wq 1=wk 2=wv
        const int t = wb & 1023;
        const int h = t >> 6;
        const int tt = t & 63;
        const int d0 = (tt >> 1) * 32;
        const int e0 = (tt & 1) * 32;
        const float* src = (arr == 0 ? wq : arr == 1 ? wk : wv) + (size_t)h * DIM * DHEAD;
        __half* dh = (arr == 0 ? g_wqh : arr == 1 ? g_wkh : g_wvh);
        __half* dl = (arr == 0 ? g_wql : arr == 1 ? g_wkl : g_wvl);
        const float scale = (arr == 0) ? QSCALE : 1.0f;

#pragma unroll
        for (int p = 0; p < 4; p++) {
            int lin = p * 256 + tid;
            int r = lin >> 5, c = lin & 31;            // r: d-offset, c: e-offset
            tile[r][c] = src[(size_t)(d0 + r) * DHEAD + e0 + c] * scale;
        }
        __syncthreads();
#pragma unroll
        for (int p = 0; p < 4; p++) {
            int lin = p * 256 + tid;
            int rr = lin >> 5, cc = lin & 31;          // rr: e-offset, cc: d-offset
            int n = h * 64 + e0 + rr;
            int k = d0 + cc;
            __half hh, ll;
            hsplit(tile[cc][rr], hh, ll);
            dh[(size_t)n * DIM + k] = hh;
            dl[(size_t)n * DIM + k] = ll;
        }
    } else {
        // wo: transpose [he=1024][d=1024] -> dst[n = d][k = he]
        const int t2 = wb - 3072;
        const int he0 = (t2 >> 5) * 32;
        const int d0 = (t2 & 31) * 32;
#pragma unroll
        for (int p = 0; p < 4; p++) {
            int lin = p * 256 + tid;
            int r = lin >> 5, c = lin & 31;            // r: he-offset, c: d-offset
            tile[r][c] = wo[(size_t)(he0 + r) * DIM + d0 + c];
        }
        __syncthreads();
#pragma unroll
        for (int p = 0; p < 4; p++) {
            int lin = p * 256 + tid;
            int rr = lin >> 5, cc = lin & 31;          // rr: d-offset, cc: he-offset
            int n = d0 + rr;
            int k = he0 + cc;
            __half hh, ll;
            hsplit(tile[cc][rr], hh, ll);
            g_woh[(size_t)n * DIM + k] = hh;
            g_wol[(size_t)n * DIM + k] = ll;
        }
    }
}

// ---------------- fp16x3 GEMM (HMMA + cp.async 2-stage) -----------------------
#define ST_AL 16384
#define ST_BH 32768
#define ST_BL 40960
#define ST_SZ 49152
#define GS2_TOTAL (2*ST_SZ)

template <bool SPLIT>
__device__ __forceinline__ void gemm_body(
    const __half* __restrict__ Ah, const __half* __restrict__ Al,
    const __half* __restrict__ Bh, const __half* __restrict__ Bl,
    float* __restrict__ C, __half* __restrict__ Ch,
    __half* __restrict__ Cl, char* smem) {
    const uint32_t sb = smem_u32(smem);
    const int tid = threadIdx.x;
    const int lane = tid & 31;
    const int wid = tid >> 5;
    const int warp_m = wid & 3;
    const int warp_n = wid >> 2;
    const int row0 = blockIdx.y * 128;
    const int col0 = blockIdx.x * 64;

    const uint4* gA[2] = {reinterpret_cast<const uint4*>(Ah + (size_t)row0 * DIM),
                          reinterpret_cast<const uint4*>(Al + (size_t)row0 * DIM)};
    const uint4* gB[2] = {reinterpret_cast<const uint4*>(Bh + (size_t)col0 * DIM),
                          reinterpret_cast<const uint4*>(Bl + (size_t)col0 * DIM)};

    const int lrow = tid >> 3, lcol = tid & 7;

    auto load_stage = [&](int cidx, int s) {
        const int k0u = cidx * 8;
        const uint32_t sbase = sb + s * ST_SZ;
#pragma unroll
        for (int m = 0; m < 2; m++) {
#pragma unroll
            for (int r4 = 0; r4 < 4; r4++) {
                int row = lrow + r4 * 32;
                uint32_t off = SWZ128(row * 128 + lcol * 16);
                cp16(sbase + (m ? ST_AL : 0) + off, gA[m] + row * 128 + k0u + lcol);
            }
#pragma unroll
            for (int r4 = 0; r4 < 2; r4++) {
                int row = lrow + r4 * 32;
                uint32_t off = SWZ128(row * 128 + lcol * 16);
                cp16(sbase + (m ? ST_BL : ST_BH) + off, gB[m] + row * 128 + k0u + lcol);
            }
        }
        CP_COMMIT();
    };

    int amask[2], abase[2];
#pragma unroll
    for (int i = 0; i < 2; i++) {
        int r = warp_m * 32 + i * 16 + (lane & 15);
        amask[i] = (r & 7) << 4;
        abase[i] = r * 128 + ((lane >> 4) & 1) * 16;
    }
    const int brow = warp_n * 32 + (lane & 7);
    const int bmaskbase = ((lane & 15) >> 3) * 16;

    float acc[2][4][4] = {};

    load_stage(0, 0);
    CP_WAIT0();
    __syncthreads();

    for (int c = 0; c < 16; c++) {
        if (c < 15) load_stage(c + 1, (c + 1) & 1);
        const uint32_t sbase = sb + (c & 1) * ST_SZ;
#pragma unroll
        for (int ks = 0; ks < 4; ks++) {
            uint32_t ah[2][4], al[2][4], bh[4][2], bl[4][2];
#pragma unroll
            for (int i = 0; i < 2; i++) {
                uint32_t offA = (abase[i] + ks * 32) ^ amask[i];
                ldsm_x4(ah[i], sbase + offA);
                ldsm_x4(al[i], sbase + ST_AL + offA);
            }
#pragma unroll
            for (int j = 0; j < 4; j++) {
                int r = brow + j * 8;
                uint32_t offB = (r * 128 + bmaskbase + ks * 32) ^ ((r & 7) << 4);
                ldsm_x2(bh[j], sbase + ST_BH + offB);
                ldsm_x2(bl[j], sbase + ST_BL + offB);
            }
#pragma unroll
            for (int i = 0; i < 2; i++)
#pragma unroll
                for (int j = 0; j < 4; j++)
                    mma_f16(acc[i][j], ah[i], bh[j]);
#pragma unroll
            for (int i = 0; i < 2; i++)
#pragma unroll
                for (int j = 0; j < 4; j++)
                    mma_f16(acc[i][j], ah[i], bl[j]);
#pragma unroll
            for (int i = 0; i < 2; i++)
#pragma unroll
                for (int j = 0; j < 4; j++)
                    mma_f16(acc[i][j], al[i], bh[j]);
        }
        if (c < 15) {
            CP_WAIT0();
            __syncthreads();
        }
    }

    const int fr = lane >> 2, fc = (lane & 3) * 2;
#pragma unroll
    for (int i = 0; i < 2; i++) {
        int rbase = row0 + warp_m * 32 + i * 16 + fr;
#pragma unroll
        for (int j = 0; j < 4; j++) {
            int col = col0 + warp_n * 32 + j * 8 + fc;
            if (SPLIT) {
                uint32_t h01, l01;
                hsplit2(acc[i][j][0], acc[i][j][1], h01, l01);
                *reinterpret_cast<uint32_t*>(&Ch[(size_t)rbase * DIM + col]) = h01;
                *reinterpret_cast<uint32_t*>(&Cl[(size_t)rbase * DIM + col]) = l01;
                hsplit2(acc[i][j][2], acc[i][j][3], h01, l01);
                *reinterpret_cast<uint32_t*>(&Ch[(size_t)(rbase + 8) * DIM + col]) = h01;
                *reinterpret_cast<uint32_t*>(&Cl[(size_t)(rbase + 8) * DIM + col]) = l01;
            } else {
                *reinterpret_cast<float2*>(&C[(size_t)rbase * DIM + col]) =
                    make_float2(acc[i][j][0], acc[i][j][1]);
                *reinterpret_cast<float2*>(&C[(size_t)(rbase + 8) * DIM + col]) =
                    make_float2(acc[i][j][2], acc[i][j][3]);
            }
        }
    }
}

struct QKVArgs {
    const __half* bh[3];
    const __half* bl[3];
    __half* ch[3];
    __half* cl[3];
};

__global__ __launch_bounds__(256, 2) void gemm_qkv(
    const __half* __restrict__ Ah, const __half* __restrict__ Al,
    QKVArgs args) {
    extern __shared__ char smem[];
    const int z = blockIdx.z;
    gemm_body<true>(Ah, Al, args.bh[z], args.bl[z], nullptr,
                    args.ch[z], args.cl[z], smem);
}

__global__ __launch_bounds__(256, 2) void gemm_wo(
    const __half* __restrict__ Ah, const __half* __restrict__ Al,
    const __half* __restrict__ Bh, const __half* __restrict__ Bl,
    float* __restrict__ C) {
    extern __shared__ char smem[];
    gemm_body<false>(Ah, Al, Bh, Bl, C, nullptr, nullptr, smem);
}

// ---------------- flash attention (fp16; QK x3 exp2 domain, PV x1) -----------
// R10 version: Q fragments re-loaded per iteration (NO hoist — hoist spills).
#define FA_QL 16384
#define FA_KV0 32768
#define FA_KVS 24576
#define FA_KL_O 8192
#define FA_VH_O 16384
#define FA_TOTAL (32768 + 2*24576)   // 81920

__global__ __launch_bounds__(256, 2) void flash_attn_mma(
    const __half* __restrict__ Qh, const __half* __restrict__ Ql,
    const __half* __restrict__ Kh, const __half* __restrict__ Kl,
    const __half* __restrict__ Vh,
    __half* __restrict__ Oh, __half* __restrict__ Ol) {
    extern __shared__ char smem[];
    const uint32_t sb = smem_u32(smem);
    const int tid = threadIdx.x, lane = tid & 31, wid = tid >> 5;
    const int qt = blockIdx.x, bhid = blockIdx.y;
    const int b = bhid >> 4, h = bhid & 15;
    const size_t base = ((size_t)(b * SEQ) * HEADS + h) * DHEAD;
    const uint4* Qhp = reinterpret_cast<const uint4*>(Qh + base);
    const uint4* Qlp = reinterpret_cast<const uint4*>(Ql + base);
    const uint4* Khp = reinterpret_cast<const uint4*>(Kh + base);
    const uint4* Klp = reinterpret_cast<const uint4*>(Kl + base);
    const uint4* Vhp = reinterpret_cast<const uint4*>(Vh + base);

    const int lrw = tid >> 3, lcl = tid & 7;

    auto load_kv = [&](int jt, int s) {
        const uint32_t kvb = sb + FA_KV0 + s * FA_KVS;
#pragma unroll
        for (int r4 = 0; r4 < 2; r4++) {
            int row = lrw + r4 * 32;
            uint32_t off = SWZ128(row * 128 + lcl * 16);
            int g = (jt * 64 + row) * 128 + lcl;
            cp16(kvb + off, Khp + g);
            cp16(kvb + FA_KL_O + off, Klp + g);
            cp16(kvb + FA_VH_O + off, Vhp + g);
        }
        CP_COMMIT();
    };

    load_kv(0, 0);
#pragma unroll
    for (int r4 = 0; r4 < 4; r4++) {
        int row = lrw + r4 * 32;
        uint32_t off = SWZ128(row * 128 + lcl * 16);
        int g = (qt * 128 + row) * 128 + lcl;
        *reinterpret_cast<uint4*>(smem + off) = Qhp[g];
        *reinterpret_cast<uint4*>(smem + FA_QL + off) = Qlp[g];
    }

    float m0 = -1e30f, m1 = -1e30f, l0 = 0.f, l1 = 0.f;
    float o[8][4] = {};
    const int fr = lane >> 2, fc = (lane & 3) * 2;
    const int qrow = wid * 16;
    const int aRow = lane & 15, aCol = (lane >> 4) * 16;
    const int kRow = ((lane >> 4) & 1) * 8 + (lane & 7);
    const int kHalf = ((lane >> 3) & 1) * 16;
    const int vRow = lane & 15;
    const int vColOff = ((lane >> 4) & 1) * 8;

    CP_WAIT0();
    __syncthreads();

    for (int jt = 0; jt < SEQ / 64; jt++) {
        const uint32_t kvb = sb + FA_KV0 + (jt & 1) * FA_KVS;
        if (jt + 1 < SEQ / 64) load_kv(jt + 1, (jt + 1) & 1);

        // ---- S = Q K^T (fp16 x3), exp2 domain ----
        float s[8][4] = {};
#pragma unroll
        for (int ks = 0; ks < 4; ks++) {
            uint32_t ah[4], al[4];
            uint32_t offA = SWZ128((qrow + aRow) * 128 + ks * 32 + aCol);
            ldsm_x4(ah, sb + offA);
            ldsm_x4(al, sb + FA_QL + offA);
#pragma unroll
            for (int jp = 0; jp < 2; jp++) {
                uint32_t kh4[2][4], kl4[2][4];
#pragma unroll
                for (int u = 0; u < 2; u++) {
                    int jj = jp * 2 + u;
                    uint32_t offB = SWZ128((jj * 16 + kRow) * 128 + ks * 32 + kHalf);
                    ldsm_x4(kh4[u], kvb + offB);
                    ldsm_x4(kl4[u], kvb + FA_KL_O + offB);
                }
#pragma unroll
                for (int u = 0; u < 2; u++) {
                    int jj = jp * 2 + u;
                    mma_f16(s[2 * jj], ah, kh4[u]);
                    mma_f16(s[2 * jj + 1], ah, kh4[u] + 2);
                }
#pragma unroll
                for (int u = 0; u < 2; u++) {
                    int jj = jp * 2 + u;
                    mma_f16(s[2 * jj], ah, kl4[u]);
                    mma_f16(s[2 * jj + 1], ah, kl4[u] + 2);
                }
#pragma unroll
                for (int u = 0; u < 2; u++) {
                    int jj = jp * 2 + u;
                    mma_f16(s[2 * jj], al, kh4[u]);
                    mma_f16(s[2 * jj + 1], al, kh4[u] + 2);
                }
            }
        }

        // ---- warp-local row max ----
        float rm0 = s[0][0], rm1 = s[0][2];
#pragma unroll
        for (int j = 0; j < 8; j++) {
            rm0 = fmaxf(rm0, fmaxf(s[j][0], s[j][1]));
            rm1 = fmaxf(rm1, fmaxf(s[j][2], s[j][3]));
        }
        rm0 = fmaxf(rm0, __shfl_xor_sync(0xffffffffu, rm0, 1));
        rm0 = fmaxf(rm0, __shfl_xor_sync(0xffffffffu, rm0, 2));
        rm1 = fmaxf(rm1, __shfl_xor_sync(0xffffffffu, rm1, 1));
        rm1 = fmaxf(rm1, __shfl_xor_sync(0xffffffffu, rm1, 2));
        float mn0 = fmaxf(m0, rm0), mn1 = fmaxf(m1, rm1);
        float a0 = ex2(m0 - mn0), a1 = ex2(m1 - mn1);
        m0 = mn0; m1 = mn1;

#pragma unroll
        for (int j = 0; j < 8; j++) {
            o[j][0] *= a0; o[j][1] *= a0;
            o[j][2] *= a1; o[j][3] *= a1;
        }

        // ---- PV x1 with fused exp2/pack ----
        float rs0 = 0.f, rs1 = 0.f;
#pragma unroll
        for (int kt = 0; kt < 4; kt++) {
            uint32_t pA[4];
#pragma unroll
            for (int u = 0; u < 2; u++) {
                int j = 2 * kt + u;
                float p0 = ex2(s[j][0] - mn0);
                float p1 = ex2(s[j][1] - mn0);
                float p2 = ex2(s[j][2] - mn1);
                float p3 = ex2(s[j][3] - mn1);
                rs0 += p0 + p1; rs1 += p2 + p3;
                __half2 t01 = __floats2half2_rn(p0, p1);
                __half2 t23 = __floats2half2_rn(p2, p3);
                pA[2 * u] = *reinterpret_cast<uint32_t*>(&t01);
                pA[2 * u + 1] = *reinterpret_cast<uint32_t*>(&t23);
            }
#pragma unroll
            for (int jj = 0; jj < 4; jj++) {
                uint32_t vh4[4];
                uint32_t offV = SWZ128((kt * 16 + vRow) * 128 + (jj * 16 + vColOff) * 2);
                ldsm_x4t(vh4, kvb + FA_VH_O + offV);
                mma_f16(o[2 * jj], pA, vh4);
                mma_f16(o[2 * jj + 1], pA, vh4 + 2);
            }
        }
        rs0 += __shfl_xor_sync(0xffffffffu, rs0, 1);
        rs0 += __shfl_xor_sync(0xffffffffu, rs0, 2);
        rs1 += __shfl_xor_sync(0xffffffffu, rs1, 1);
        rs1 += __shfl_xor_sync(0xffffffffu, rs1, 2);
        l0 = l0 * a0 + rs0;
        l1 = l1 * a1 + rs1;

        if (jt + 1 < SEQ / 64) CP_WAIT0();
        __syncthreads();
    }

    // ---- epilogue: normalize, split, store [b,n,h,e] ----
    float inv0 = 1.f / l0, inv1 = 1.f / l1;
    const int r0g = qt * 128 + qrow + fr;
#pragma unroll
    for (int j = 0; j < 8; j++) {
        int col = j * 8 + fc;
        uint32_t h01, l01;
        hsplit2(o[j][0] * inv0, o[j][1] * inv0, h01, l01);
        *reinterpret_cast<uint32_t*>(Oh + base + (size_t)r0g * 1024 + col) = h01;
        *reinterpret_cast<uint32_t*>(Ol + base + (size_t)r0g * 1024 + col) = l01;
        hsplit2(o[j][2] * inv1, o[j][3] * inv1, h01, l01);
        *reinterpret_cast<uint32_t*>(Oh + base + (size_t)(r0g + 8) * 1024 + col) = h01;
        *reinterpret_cast<uint32_t*>(Ol + base + (size_t)(r0g + 8) * 1024 + col) = l01;
    }
}

// ---------------- launch ------------------------------------------------------
extern "C" void kernel_launch(void* const* d_in, const int* in_sizes, int n_in,
                              void* d_out, int out_size) {
    const float* tokens = (const float*)d_in[0];
    const float* wq = (const float*)d_in[1];
    const float* wk = (const float*)d_in[2];
    const float* wv = (const float*)d_in[3];
    const float* wo = (const float*)d_in[4];
    float* out = (float*)d_out;

    __half *tokh, *tokl, *qh, *ql, *kh, *kl, *vh, *vl, *aggh, *aggl;
    __half *wqh, *wql, *wkh, *wkl, *wvh, *wvl, *woh, *wol;
    cudaGetSymbolAddress((void**)&tokh, g_tokh);
    cudaGetSymbolAddress((void**)&tokl, g_tokl);
    cudaGetSymbolAddress((void**)&qh, g_qh);
    cudaGetSymbolAddress((void**)&ql, g_ql);
    cudaGetSymbolAddress((void**)&kh, g_kh);
    cudaGetSymbolAddress((void**)&kl, g_kl);
    cudaGetSymbolAddress((void**)&vh, g_vh);
    cudaGetSymbolAddress((void**)&vl, g_vl);
    cudaGetSymbolAddress((void**)&aggh, g_aggh);
    cudaGetSymbolAddress((void**)&aggl, g_aggl);
    cudaGetSymbolAddress((void**)&wqh, g_wqh);
    cudaGetSymbolAddress((void**)&wql, g_wql);
    cudaGetSymbolAddress((void**)&wkh, g_wkh);
    cudaGetSymbolAddress((void**)&wkl, g_wkl);
    cudaGetSymbolAddress((void**)&wvh, g_wvh);
    cudaGetSymbolAddress((void**)&wvl, g_wvl);
    cudaGetSymbolAddress((void**)&woh, g_woh);
    cudaGetSymbolAddress((void**)&wol, g_wol);

    prep_all<<<8192, 256>>>((const float4*)tokens, wq, wk, wv, wo);

    cudaFuncSetAttribute(gemm_qkv, cudaFuncAttributeMaxDynamicSharedMemorySize,
                         GS2_TOTAL);
    cudaFuncSetAttribute(gemm_wo, cudaFuncAttributeMaxDynamicSharedMemorySize,
                         GS2_TOTAL);

    QKVArgs args;
    args.bh[0] = wqh; args.bl[0] = wql; args.ch[0] = qh; args.cl[0] = ql;
    args.bh[1] = wkh; args.bl[1] = wkl; args.ch[1] = kh; args.cl[1] = kl;
    args.bh[2] = wvh; args.bl[2] = wvl; args.ch[2] = vh; args.cl[2] = vl;

    dim3 gqkv(DIM / 64, BS / 128, 3);
    gemm_qkv<<<gqkv, 256, GS2_TOTAL>>>(tokh, tokl, args);

    cudaFuncSetAttribute(flash_attn_mma,
                         cudaFuncAttributeMaxDynamicSharedMemorySize, FA_TOTAL);
    flash_attn_mma<<<dim3(SEQ / 128, BATCH * HEADS), 256, FA_TOTAL>>>(
        qh, ql, kh, kl, vh, aggh, aggl);

    dim3 gp(DIM / 64, BS / 128);
    gemm_wo<<<gp, 256, GS2_TOTAL>>>(aggh, aggl, woh, wol, out);
}

// round 13
// speedup vs baseline: 1.5465x; 1.4932x over previous
#include <cuda_runtime.h>
#include <cuda_fp16.h>
#include <cstdint>

#define BATCH 2
#define SEQ 2048
#define DIM 1024
#define HEADS 16
#define DHEAD 64
#define BS (BATCH*SEQ)   // 4096

// ---------------- scratch (device globals; no allocations allowed) ----------
__device__ __half g_tokh[BS*DIM], g_tokl[BS*DIM];
__device__ __half g_qh[BS*DIM], g_ql[BS*DIM];
__device__ __half g_kh[BS*DIM], g_kl[BS*DIM];
__device__ __half g_vh[BS*DIM], g_vl[BS*DIM];
__device__ __half g_aggh[BS*DIM], g_aggl[BS*DIM];
__device__ __half g_wqh[DIM*DIM], g_wql[DIM*DIM];
__device__ __half g_wkh[DIM*DIM], g_wkl[DIM*DIM];
__device__ __half g_wvh[DIM*DIM], g_wvl[DIM*DIM];
__device__ __half g_woh[DIM*DIM], g_wol[DIM*DIM];

// ---------------- helpers ----------------------------------------------------
__device__ __forceinline__ uint32_t smem_u32(const void* p) {
    uint32_t a;
    asm("{ .reg .u64 t; cvta.to.shared.u64 t, %1; cvt.u32.u64 %0, t; }"
        : "=r"(a) : "l"(p));
    return a;
}
#define SWZ128(o) ((o) ^ (((o) >> 3) & 0x70))

__device__ __forceinline__ void cp16(uint32_t saddr, const void* gptr) {
    asm volatile("cp.async.cg.shared.global [%0], [%1], 16;"
                 :: "r"(saddr), "l"(gptr));
}
#define CP_COMMIT() asm volatile("cp.async.commit_group;" ::: "memory")
#define CP_WAIT0()  asm volatile("cp.async.wait_group 0;" ::: "memory")

__device__ __forceinline__ void ldsm_x4(uint32_t* r, uint32_t addr) {
    asm volatile("ldmatrix.sync.aligned.m8n8.x4.shared.b16 {%0,%1,%2,%3}, [%4];"
                 : "=r"(r[0]), "=r"(r[1]), "=r"(r[2]), "=r"(r[3]) : "r"(addr));
}
__device__ __forceinline__ void ldsm_x2(uint32_t* r, uint32_t addr) {
    asm volatile("ldmatrix.sync.aligned.m8n8.x2.shared.b16 {%0,%1}, [%2];"
                 : "=r"(r[0]), "=r"(r[1]) : "r"(addr));
}
__device__ __forceinline__ void ldsm_x4t(uint32_t* r, uint32_t addr) {
    asm volatile("ldmatrix.sync.aligned.m8n8.x4.trans.shared.b16 {%0,%1,%2,%3}, [%4];"
                 : "=r"(r[0]), "=r"(r[1]), "=r"(r[2]), "=r"(r[3]) : "r"(addr));
}
__device__ __forceinline__ void mma_f16(float* c, const uint32_t* a, const uint32_t* b) {
    asm volatile(
        "mma.sync.aligned.m16n8k16.row.col.f32.f16.f16.f32 "
        "{%0,%1,%2,%3}, {%4,%5,%6,%7}, {%8,%9}, {%0,%1,%2,%3};"
        : "+f"(c[0]), "+f"(c[1]), "+f"(c[2]), "+f"(c[3])
        : "r"(a[0]), "r"(a[1]), "r"(a[2]), "r"(a[3]), "r"(b[0]), "r"(b[1]));
}
__device__ __forceinline__ float ex2(float x) {
    float y;
    asm("ex2.approx.ftz.f32 %0, %1;" : "=f"(y) : "f"(x));
    return y;
}
__device__ __forceinline__ void hsplit(float v, __half& h, __half& l) {
    h = __float2half_rn(v);
    l = __float2half_rn(v - __half2float(h));
}
__device__ __forceinline__ void hsplit2(float a, float b, uint32_t& hi, uint32_t& lo) {
    __half2 h = __floats2half2_rn(a, b);
    float2 f = __half22float2(h);
    __half2 l = __floats2half2_rn(a - f.x, b - f.y);
    hi = *reinterpret_cast<uint32_t*>(&h);
    lo = *reinterpret_cast<uint32_t*>(&l);
}

// ---------------- split / pack kernels ---------------------------------------
__global__ void split_act(const float4* __restrict__ x,
                          __half* __restrict__ hi,
                          __half* __restrict__ lo, int n4) {
    int i = blockIdx.x * blockDim.x + threadIdx.x;
    if (i >= n4) return;
    float4 v = x[i];
    uint32_t h01, l01, h23, l23;
    hsplit2(v.x, v.y, h01, l01);
    hsplit2(v.z, v.w, h23, l23);
    uint32_t* H = reinterpret_cast<uint32_t*>(hi);
    uint32_t* L = reinterpret_cast<uint32_t*>(lo);
    H[2 * i] = h01; H[2 * i + 1] = h23;
    L[2 * i] = l01; L[2 * i + 1] = l23;
}

// q scale folds SCALE and log2(e) so softmax runs in exp2 domain
#define QSCALE 0.18033688011112042f   // 0.125 * log2(e)

__global__ void pack_w(const float* __restrict__ wq, const float* __restrict__ wk,
                       const float* __restrict__ wv, const float* __restrict__ wo) {
    int idx = blockIdx.x * blockDim.x + threadIdx.x;
    if (idx >= DIM * DIM) return;
    int n = idx >> 10;
    int k = idx & 1023;
    int h = n >> 6, e = n & 63;
    int src = (h * DIM + k) * DHEAD + e;
    hsplit(wq[src] * QSCALE, g_wqh[idx], g_wql[idx]);
    hsplit(wk[src], g_wkh[idx], g_wkl[idx]);
    hsplit(wv[src], g_wvh[idx], g_wvl[idx]);
    hsplit(wo[k * DIM + n], g_woh[idx], g_wol[idx]);
}

// ---------------- fp16x3 GEMM (HMMA + cp.async 2-stage) -----------------------
#define ST_AL 16384
#define ST_BH 32768
#define ST_BL 40960
#define ST_SZ 49152
#define GS2_TOTAL (2*ST_SZ)

template <bool SPLIT>
__device__ __forceinline__ void gemm_body(
    const __half* __restrict__ Ah, const __half* __restrict__ Al,
    const __half* __restrict__ Bh, const __half* __restrict__ Bl,
    float* __restrict__ C, __half* __restrict__ Ch,
    __half* __restrict__ Cl, char* smem) {
    const uint32_t sb = smem_u32(smem);
    const int tid = threadIdx.x;
    const int lane = tid & 31;
    const int wid = tid >> 5;
    const int warp_m = wid & 3;
    const int warp_n = wid >> 2;
    const int row0 = blockIdx.y * 128;
    const int col0 = blockIdx.x * 64;

    const uint4* gA[2] = {reinterpret_cast<const uint4*>(Ah + (size_t)row0 * DIM),
                          reinterpret_cast<const uint4*>(Al + (size_t)row0 * DIM)};
    const uint4* gB[2] = {reinterpret_cast<const uint4*>(Bh + (size_t)col0 * DIM),
                          reinterpret_cast<const uint4*>(Bl + (size_t)col0 * DIM)};

    const int lrow = tid >> 3, lcol = tid & 7;

    auto load_stage = [&](int cidx, int s) {
        const int k0u = cidx * 8;
        const uint32_t sbase = sb + s * ST_SZ;
#pragma unroll
        for (int m = 0; m < 2; m++) {
#pragma unroll
            for (int r4 = 0; r4 < 4; r4++) {
                int row = lrow + r4 * 32;
                uint32_t off = SWZ128(row * 128 + lcol * 16);
                cp16(sbase + (m ? ST_AL : 0) + off, gA[m] + row * 128 + k0u + lcol);
            }
#pragma unroll
            for (int r4 = 0; r4 < 2; r4++) {
                int row = lrow + r4 * 32;
                uint32_t off = SWZ128(row * 128 + lcol * 16);
                cp16(sbase + (m ? ST_BL : ST_BH) + off, gB[m] + row * 128 + k0u + lcol);
            }
        }
        CP_COMMIT();
    };

    int amask[2], abase[2];
#pragma unroll
    for (int i = 0; i < 2; i++) {
        int r = warp_m * 32 + i * 16 + (lane & 15);
        amask[i] = (r & 7) << 4;
        abase[i] = r * 128 + ((lane >> 4) & 1) * 16;
    }
    const int brow = warp_n * 32 + (lane & 7);
    const int bmaskbase = ((lane & 15) >> 3) * 16;

    float acc[2][4][4] = {};

    load_stage(0, 0);
    CP_WAIT0();
    __syncthreads();

    for (int c = 0; c < 16; c++) {
        if (c < 15) load_stage(c + 1, (c + 1) & 1);
        const uint32_t sbase = sb + (c & 1) * ST_SZ;
#pragma unroll
        for (int ks = 0; ks < 4; ks++) {
            uint32_t ah[2][4], al[2][4], bh[4][2], bl[4][2];
#pragma unroll
            for (int i = 0; i < 2; i++) {
                uint32_t offA = (abase[i] + ks * 32) ^ amask[i];
                ldsm_x4(ah[i], sbase + offA);
                ldsm_x4(al[i], sbase + ST_AL + offA);
            }
#pragma unroll
            for (int j = 0; j < 4; j++) {
                int r = brow + j * 8;
                uint32_t offB = (r * 128 + bmaskbase + ks * 32) ^ ((r & 7) << 4);
                ldsm_x2(bh[j], sbase + ST_BH + offB);
                ldsm_x2(bl[j], sbase + ST_BL + offB);
            }
#pragma unroll
            for (int i = 0; i < 2; i++)
#pragma unroll
                for (int j = 0; j < 4; j++)
                    mma_f16(acc[i][j], ah[i], bh[j]);
#pragma unroll
            for (int i = 0; i < 2; i++)
#pragma unroll
                for (int j = 0; j < 4; j++)
                    mma_f16(acc[i][j], ah[i], bl[j]);
#pragma unroll
            for (int i = 0; i < 2; i++)
#pragma unroll
                for (int j = 0; j < 4; j++)
                    mma_f16(acc[i][j], al[i], bh[j]);
        }
        if (c < 15) {
            CP_WAIT0();
            __syncthreads();
        }
    }

    const int fr = lane >> 2, fc = (lane & 3) * 2;
#pragma unroll
    for (int i = 0; i < 2; i++) {
        int rbase = row0 + warp_m * 32 + i * 16 + fr;
#pragma unroll
        for (int j = 0; j < 4; j++) {
            int col = col0 + warp_n * 32 + j * 8 + fc;
            if (SPLIT) {
                uint32_t h01, l01;
                hsplit2(acc[i][j][0], acc[i][j][1], h01, l01);
                *reinterpret_cast<uint32_t*>(&Ch[(size_t)rbase * DIM + col]) = h01;
                *reinterpret_cast<uint32_t*>(&Cl[(size_t)rbase * DIM + col]) = l01;
                hsplit2(acc[i][j][2], acc[i][j][3], h01, l01);
                *reinterpret_cast<uint32_t*>(&Ch[(size_t)(rbase + 8) * DIM + col]) = h01;
                *reinterpret_cast<uint32_t*>(&Cl[(size_t)(rbase + 8) * DIM + col]) = l01;
            } else {
                *reinterpret_cast<float2*>(&C[(size_t)rbase * DIM + col]) =
                    make_float2(acc[i][j][0], acc[i][j][1]);
                *reinterpret_cast<float2*>(&C[(size_t)(rbase + 8) * DIM + col]) =
                    make_float2(acc[i][j][2], acc[i][j][3]);
            }
        }
    }
}

struct QKVArgs {
    const __half* bh[3];
    const __half* bl[3];
    __half* ch[3];
    __half* cl[3];
};

__global__ __launch_bounds__(256, 2) void gemm_qkv(
    const __half* __restrict__ Ah, const __half* __restrict__ Al,
    QKVArgs args) {
    extern __shared__ char smem[];
    const int z = blockIdx.z;
    gemm_body<true>(Ah, Al, args.bh[z], args.bl[z], nullptr,
                    args.ch[z], args.cl[z], smem);
}

__global__ __launch_bounds__(256, 2) void gemm_wo(
    const __half* __restrict__ Ah, const __half* __restrict__ Al,
    const __half* __restrict__ Bh, const __half* __restrict__ Bl,
    float* __restrict__ C) {
    extern __shared__ char smem[];
    gemm_body<false>(Ah, Al, Bh, Bl, C, nullptr, nullptr, smem);
}

// ---------------- flash attention (fp16; QK x3 in exp2 domain, PV x1) --------
#define FA_QL 16384
#define FA_KV0 32768
#define FA_KVS 24576
#define FA_KL_O 8192
#define FA_VH_O 16384
#define FA_TOTAL (32768 + 2*24576)   // 81920

__global__ __launch_bounds__(256, 2) void flash_attn_mma(
    const __half* __restrict__ Qh, const __half* __restrict__ Ql,
    const __half* __restrict__ Kh, const __half* __restrict__ Kl,
    const __half* __restrict__ Vh,
    __half* __restrict__ Oh, __half* __restrict__ Ol) {
    extern __shared__ char smem[];
    const uint32_t sb = smem_u32(smem);
    const int tid = threadIdx.x, lane = tid & 31, wid = tid >> 5;
    const int qt = blockIdx.x, bhid = blockIdx.y;
    const int b = bhid >> 4, h = bhid & 15;
    const size_t base = ((size_t)(b * SEQ) * HEADS + h) * DHEAD;
    const uint4* Qhp = reinterpret_cast<const uint4*>(Qh + base);
    const uint4* Qlp = reinterpret_cast<const uint4*>(Ql + base);
    const uint4* Khp = reinterpret_cast<const uint4*>(Kh + base);
    const uint4* Klp = reinterpret_cast<const uint4*>(Kl + base);
    const uint4* Vhp = reinterpret_cast<const uint4*>(Vh + base);

    const int lrw = tid >> 3, lcl = tid & 7;

    auto load_kv = [&](int jt, int s) {
        const uint32_t kvb = sb + FA_KV0 + s * FA_KVS;
#pragma unroll
        for (int r4 = 0; r4 < 2; r4++) {
            int row = lrw + r4 * 32;
            uint32_t off = SWZ128(row * 128 + lcl * 16);
            int g = (jt * 64 + row) * 128 + lcl;
            cp16(kvb + off, Khp + g);
            cp16(kvb + FA_KL_O + off, Klp + g);
            cp16(kvb + FA_VH_O + off, Vhp + g);
        }
        CP_COMMIT();
    };

    load_kv(0, 0);
#pragma unroll
    for (int r4 = 0; r4 < 4; r4++) {
        int row = lrw + r4 * 32;
        uint32_t off = SWZ128(row * 128 + lcl * 16);
        int g = (qt * 128 + row) * 128 + lcl;
        *reinterpret_cast<uint4*>(smem + off) = Qhp[g];
        *reinterpret_cast<uint4*>(smem + FA_QL + off) = Qlp[g];
    }

    float m0 = -1e30f, m1 = -1e30f, l0 = 0.f, l1 = 0.f;
    float o[8][4] = {};
    const int fr = lane >> 2, fc = (lane & 3) * 2;
    const int qrow = wid * 16;
    const int aRow = lane & 15, aCol = (lane >> 4) * 16;
    const int kRow = ((lane >> 4) & 1) * 8 + (lane & 7);
    const int kHalf = ((lane >> 3) & 1) * 16;
    const int vRow = lane & 15;
    const int vColOff = ((lane >> 4) & 1) * 8;

    CP_WAIT0();
    __syncthreads();

    for (int jt = 0; jt < SEQ / 64; jt++) {
        const uint32_t kvb = sb + FA_KV0 + (jt & 1) * FA_KVS;
        if (jt + 1 < SEQ / 64) load_kv(jt + 1, (jt + 1) & 1);

        // ---- S = Q K^T (fp16 x3), exp2 domain ----
        float s[8][4] = {};
#pragma unroll
        for (int ks = 0; ks < 4; ks++) {
            uint32_t ah[4], al[4];
            uint32_t offA = SWZ128((qrow + aRow) * 128 + ks * 32 + aCol);
            ldsm_x4(ah, sb + offA);
            ldsm_x4(al, sb + FA_QL + offA);
#pragma unroll
            for (int jp = 0; jp < 2; jp++) {
                uint32_t kh4[2][4], kl4[2][4];
#pragma unroll
                for (int u = 0; u < 2; u++) {
                    int jj = jp * 2 + u;
                    uint32_t offB = SWZ128((jj * 16 + kRow) * 128 + ks * 32 + kHalf);
                    ldsm_x4(kh4[u], kvb + offB);
                    ldsm_x4(kl4[u], kvb + FA_KL_O + offB);
                }
#pragma unroll
                for (int u = 0; u < 2; u++) {
                    int jj = jp * 2 + u;
                    mma_f16(s[2 * jj], ah, kh4[u]);
                    mma_f16(s[2 * jj + 1], ah, kh4[u] + 2);
                }
#pragma unroll
                for (int u = 0; u < 2; u++) {
                    int jj = jp * 2 + u;
                    mma_f16(s[2 * jj], ah, kl4[u]);
                    mma_f16(s[2 * jj + 1], ah, kl4[u] + 2);
                }
#pragma unroll
                for (int u = 0; u < 2; u++) {
                    int jj = jp * 2 + u;
                    mma_f16(s[2 * jj], al, kh4[u]);
                    mma_f16(s[2 * jj + 1], al, kh4[u] + 2);
                }
            }
        }

        // ---- warp-local row max ----
        float rm0 = s[0][0], rm1 = s[0][2];
#pragma unroll
        for (int j = 0; j < 8; j++) {
            rm0 = fmaxf(rm0, fmaxf(s[j][0], s[j][1]));
            rm1 = fmaxf(rm1, fmaxf(s[j][2], s[j][3]));
        }
        rm0 = fmaxf(rm0, __shfl_xor_sync(0xffffffffu, rm0, 1));
        rm0 = fmaxf(rm0, __shfl_xor_sync(0xffffffffu, rm0, 2));
        rm1 = fmaxf(rm1, __shfl_xor_sync(0xffffffffu, rm1, 1));
        rm1 = fmaxf(rm1, __shfl_xor_sync(0xffffffffu, rm1, 2));
        float mn0 = fmaxf(m0, rm0), mn1 = fmaxf(m1, rm1);
        float a0 = ex2(m0 - mn0), a1 = ex2(m1 - mn1);
        m0 = mn0; m1 = mn1;

#pragma unroll
        for (int j = 0; j < 8; j++) {
            o[j][0] *= a0; o[j][1] *= a0;
            o[j][2] *= a1; o[j][3] *= a1;
        }

        // ---- PV x1 with fused exp2/pack ----
        float rs0 = 0.f, rs1 = 0.f;
#pragma unroll
        for (int kt = 0; kt < 4; kt++) {
            uint32_t pA[4];
#pragma unroll
            for (int u = 0; u < 2; u++) {
                int j = 2 * kt + u;
                float p0 = ex2(s[j][0] - mn0);
                float p1 = ex2(s[j][1] - mn0);
                float p2 = ex2(s[j][2] - mn1);
                float p3 = ex2(s[j][3] - mn1);
                rs0 += p0 + p1; rs1 += p2 + p3;
                __half2 t01 = __floats2half2_rn(p0, p1);
                __half2 t23 = __floats2half2_rn(p2, p3);
                pA[2 * u] = *reinterpret_cast<uint32_t*>(&t01);
                pA[2 * u + 1] = *reinterpret_cast<uint32_t*>(&t23);
            }
#pragma unroll
            for (int jj = 0; jj < 4; jj++) {
                uint32_t vh4[4];
                uint32_t offV = SWZ128((kt * 16 + vRow) * 128 + (jj * 16 + vColOff) * 2);
                ldsm_x4t(vh4, kvb + FA_VH_O + offV);
                mma_f16(o[2 * jj], pA, vh4);
                mma_f16(o[2 * jj + 1], pA, vh4 + 2);
            }
        }
        rs0 += __shfl_xor_sync(0xffffffffu, rs0, 1);
        rs0 += __shfl_xor_sync(0xffffffffu, rs0, 2);
        rs1 += __shfl_xor_sync(0xffffffffu, rs1, 1);
        rs1 += __shfl_xor_sync(0xffffffffu, rs1, 2);
        l0 = l0 * a0 + rs0;
        l1 = l1 * a1 + rs1;

        if (jt + 1 < SEQ / 64) CP_WAIT0();
        __syncthreads();
    }

    // ---- epilogue: normalize, split, store [b,n,h,e] ----
    float inv0 = 1.f / l0, inv1 = 1.f / l1;
    const int r0g = qt * 128 + qrow + fr;
#pragma unroll
    for (int j = 0; j < 8; j++) {
        int col = j * 8 + fc;
        uint32_t h01, l01;
        hsplit2(o[j][0] * inv0, o[j][1] * inv0, h01, l01);
        *reinterpret_cast<uint32_t*>(Oh + base + (size_t)r0g * 1024 + col) = h01;
        *reinterpret_cast<uint32_t*>(Ol + base + (size_t)r0g * 1024 + col) = l01;
        hsplit2(o[j][2] * inv1, o[j][3] * inv1, h01, l01);
        *reinterpret_cast<uint32_t*>(Oh + base + (size_t)(r0g + 8) * 1024 + col) = h01;
        *reinterpret_cast<uint32_t*>(Ol + base + (size_t)(r0g + 8) * 1024 + col) = l01;
    }
}

// ---------------- launch ------------------------------------------------------
extern "C" void kernel_launch(void* const* d_in, const int* in_sizes, int n_in,
                              void* d_out, int out_size) {
    const float* tokens = (const float*)d_in[0];
    const float* wq = (const float*)d_in[1];
    const float* wk = (const float*)d_in[2];
    const float* wv = (const float*)d_in[3];
    const float* wo = (const float*)d_in[4];
    float* out = (float*)d_out;

    __half *tokh, *tokl, *qh, *ql, *kh, *kl, *vh, *vl, *aggh, *aggl;
    __half *wqh, *wql, *wkh, *wkl, *wvh, *wvl, *woh, *wol;
    cudaGetSymbolAddress((void**)&tokh, g_tokh);
    cudaGetSymbolAddress((void**)&tokl, g_tokl);
    cudaGetSymbolAddress((void**)&qh, g_qh);
    cudaGetSymbolAddress((void**)&ql, g_ql);
    cudaGetSymbolAddress((void**)&kh, g_kh);
    cudaGetSymbolAddress((void**)&kl, g_kl);
    cudaGetSymbolAddress((void**)&vh, g_vh);
    cudaGetSymbolAddress((void**)&vl, g_vl);
    cudaGetSymbolAddress((void**)&aggh, g_aggh);
    cudaGetSymbolAddress((void**)&aggl, g_aggl);
    cudaGetSymbolAddress((void**)&wqh, g_wqh);
    cudaGetSymbolAddress((void**)&wql, g_wql);
    cudaGetSymbolAddress((void**)&wkh, g_wkh);
    cudaGetSymbolAddress((void**)&wkl, g_wkl);
    cudaGetSymbolAddress((void**)&wvh, g_wvh);
    cudaGetSymbolAddress((void**)&wvl, g_wvl);
    cudaGetSymbolAddress((void**)&woh, g_woh);
    cudaGetSymbolAddress((void**)&wol, g_wol);

    split_act<<<(BS * DIM / 4 + 255) / 256, 256>>>(
        (const float4*)tokens, tokh, tokl, BS * DIM / 4);
    pack_w<<<(DIM * DIM + 255) / 256, 256>>>(wq, wk, wv, wo);

    cudaFuncSetAttribute(gemm_qkv, cudaFuncAttributeMaxDynamicSharedMemorySize,
                         GS2_TOTAL);
    cudaFuncSetAttribute(gemm_wo, cudaFuncAttributeMaxDynamicSharedMemorySize,
                         GS2_TOTAL);

    QKVArgs args;
    args.bh[0] = wqh; args.bl[0] = wql; args.ch[0] = qh; args.cl[0] = ql;
    args.bh[1] = wkh; args.bl[1] = wkl; args.ch[1] = kh; args.cl[1] = kl;
    args.bh[2] = wvh; args.bl[2] = wvl; args.ch[2] = vh; args.cl[2] = vl;

    dim3 gqkv(DIM / 64, BS / 128, 3);
    gemm_qkv<<<gqkv, 256, GS2_TOTAL>>>(tokh, tokl, args);

    cudaFuncSetAttribute(flash_attn_mma,
                         cudaFuncAttributeMaxDynamicSharedMemorySize, FA_TOTAL);
    flash_attn_mma<<<dim3(SEQ / 128, BATCH * HEADS), 256, FA_TOTAL>>>(
        qh, ql, kh, kl, vh, aggh, aggl);

    dim3 gp(DIM / 64, BS / 128);
    gemm_wo<<<gp, 256, GS2_TOTAL>>>(aggh, aggl, woh, wol, out);
}

// round 14
// speedup vs baseline: 1.5841x; 1.0243x over previous
#include <cuda_runtime.h>
#include <cuda_fp16.h>
#include <cstdint>

#define BATCH 2
#define SEQ 2048
#define DIM 1024
#define HEADS 16
#define DHEAD 64
#define BS (BATCH*SEQ)   // 4096

// ---------------- scratch (device globals; no allocations allowed) ----------
__device__ __half g_tokh[BS*DIM], g_tokl[BS*DIM];
__device__ __half g_qh[BS*DIM], g_ql[BS*DIM];
__device__ __half g_kh[BS*DIM], g_kl[BS*DIM];
__device__ __half g_vh[BS*DIM], g_vl[BS*DIM];
__device__ __half g_aggh[BS*DIM], g_aggl[BS*DIM];
__device__ __half g_wqh[DIM*DIM], g_wql[DIM*DIM];
__device__ __half g_wkh[DIM*DIM], g_wkl[DIM*DIM];
__device__ __half g_wvh[DIM*DIM], g_wvl[DIM*DIM];
__device__ __half g_woh[DIM*DIM], g_wol[DIM*DIM];

// ---------------- helpers ----------------------------------------------------
__device__ __forceinline__ uint32_t smem_u32(const void* p) {
    uint32_t a;
    asm("{ .reg .u64 t; cvta.to.shared.u64 t, %1; cvt.u32.u64 %0, t; }"
        : "=r"(a) : "l"(p));
    return a;
}
#define SWZ128(o) ((o) ^ (((o) >> 3) & 0x70))

__device__ __forceinline__ void cp16(uint32_t saddr, const void* gptr) {
    asm volatile("cp.async.cg.shared.global [%0], [%1], 16;"
                 :: "r"(saddr), "l"(gptr));
}
#define CP_COMMIT() asm volatile("cp.async.commit_group;" ::: "memory")
#define CP_WAIT0()  asm volatile("cp.async.wait_group 0;" ::: "memory")

__device__ __forceinline__ void ldsm_x4(uint32_t* r, uint32_t addr) {
    asm volatile("ldmatrix.sync.aligned.m8n8.x4.shared.b16 {%0,%1,%2,%3}, [%4];"
                 : "=r"(r[0]), "=r"(r[1]), "=r"(r[2]), "=r"(r[3]) : "r"(addr));
}
__device__ __forceinline__ void ldsm_x4t(uint32_t* r, uint32_t addr) {
    asm volatile("ldmatrix.sync.aligned.m8n8.x4.trans.shared.b16 {%0,%1,%2,%3}, [%4];"
                 : "=r"(r[0]), "=r"(r[1]), "=r"(r[2]), "=r"(r[3]) : "r"(addr));
}
__device__ __forceinline__ void mma_f16(float* c, const uint32_t* a, const uint32_t* b) {
    asm volatile(
        "mma.sync.aligned.m16n8k16.row.col.f32.f16.f16.f32 "
        "{%0,%1,%2,%3}, {%4,%5,%6,%7}, {%8,%9}, {%0,%1,%2,%3};"
        : "+f"(c[0]), "+f"(c[1]), "+f"(c[2]), "+f"(c[3])
        : "r"(a[0]), "r"(a[1]), "r"(a[2]), "r"(a[3]), "r"(b[0]), "r"(b[1]));
}
__device__ __forceinline__ float ex2(float x) {
    float y;
    asm("ex2.approx.ftz.f32 %0, %1;" : "=f"(y) : "f"(x));
    return y;
}
__device__ __forceinline__ void hsplit(float v, __half& h, __half& l) {
    h = __float2half_rn(v);
    l = __float2half_rn(v - __half2float(h));
}
__device__ __forceinline__ void hsplit2(float a, float b, uint32_t& hi, uint32_t& lo) {
    __half2 h = __floats2half2_rn(a, b);
    float2 f = __half22float2(h);
    __half2 l = __floats2half2_rn(a - f.x, b - f.y);
    hi = *reinterpret_cast<uint32_t*>(&h);
    lo = *reinterpret_cast<uint32_t*>(&l);
}

// ---------------- fused prep: token split + coalesced weight transpose ------
// blocks [0, 4096): split tokens (1M float4)
// blocks [4096, 8192): 32x32-tile transposes of wq/wk/wv (per-head) and wo
#define QSCALE 0.18033688011112042f   // 0.125 * log2(e)

__global__ void prep_all(const float4* __restrict__ tok,
                         const float* __restrict__ wq, const float* __restrict__ wk,
                         const float* __restrict__ wv, const float* __restrict__ wo) {
    __shared__ float tile[32][33];
    const int blk = blockIdx.x;
    const int tid = threadIdx.x;

    if (blk < 4096) {
        int i = blk * 256 + tid;          // < 1048576 = BS*DIM/4
        float4 v = tok[i];
        uint32_t h01, l01, h23, l23;
        hsplit2(v.x, v.y, h01, l01);
        hsplit2(v.z, v.w, h23, l23);
        uint32_t* H = reinterpret_cast<uint32_t*>(g_tokh);
        uint32_t* L = reinterpret_cast<uint32_t*>(g_tokl);
        H[2 * i] = h01; H[2 * i + 1] = h23;
        L[2 * i] = l01; L[2 * i + 1] = l23;
        return;
    }

    const int wb = blk - 4096;            // [0, 4096)
    if (wb < 3072) {
        // qkv: per-head transpose [1024 d][64 e] -> dst[n = h*64+e][k = d]
        const int arr = wb >> 10;         // 0=wq 1=wk 2=wv
        const int t = wb & 1023;
        const int h = t >> 6;
        const int tt = t & 63;
        const int d0 = (tt >> 1) * 32;
        const int e0 = (tt & 1) * 32;
        const float* src = (arr == 0 ? wq : arr == 1 ? wk : wv) + (size_t)h * DIM * DHEAD;
        __half* dh = (arr == 0 ? g_wqh : arr == 1 ? g_wkh : g_wvh);
        __half* dl = (arr == 0 ? g_wql : arr == 1 ? g_wkl : g_wvl);
        const float scale = (arr == 0) ? QSCALE : 1.0f;

#pragma unroll
        for (int p = 0; p < 4; p++) {
            int lin = p * 256 + tid;
            int r = lin >> 5, c = lin & 31;            // r: d-offset, c: e-offset
            tile[r][c] = src[(size_t)(d0 + r) * DHEAD + e0 + c] * scale;
        }
        __syncthreads();
#pragma unroll
        for (int p = 0; p < 4; p++) {
            int lin = p * 256 + tid;
            int rr = lin >> 5, cc = lin & 31;          // rr: e-offset, cc: d-offset
            int n = h * 64 + e0 + rr;
            int k = d0 + cc;
            __half hh, ll;
            hsplit(tile[cc][rr], hh, ll);
            dh[(size_t)n * DIM + k] = hh;
            dl[(size_t)n * DIM + k] = ll;
        }
    } else {
        // wo: transpose [he=1024][d=1024] -> dst[n = d][k = he]
        const int t2 = wb - 3072;
        const int he0 = (t2 >> 5) * 32;
        const int d0 = (t2 & 31) * 32;
#pragma unroll
        for (int p = 0; p < 4; p++) {
            int lin = p * 256 + tid;
            int r = lin >> 5, c = lin & 31;            // r: he-offset, c: d-offset
            tile[r][c] = wo[(size_t)(he0 + r) * DIM + d0 + c];
        }
        __syncthreads();
#pragma unroll
        for (int p = 0; p < 4; p++) {
            int lin = p * 256 + tid;
            int rr = lin >> 5, cc = lin & 31;          // rr: d-offset, cc: he-offset
            int n = d0 + rr;
            int k = he0 + cc;
            __half hh, ll;
            hsplit(tile[cc][rr], hh, ll);
            g_woh[(size_t)n * DIM + k] = hh;
            g_wol[(size_t)n * DIM + k] = ll;
        }
    }
}

// ---------------- fp16x3 GEMM (HMMA + cp.async 2-stage) -----------------------
#define ST_AL 16384
#define ST_BH 32768
#define ST_BL 40960
#define ST_SZ 49152
#define GS2_TOTAL (2*ST_SZ)

template <bool SPLIT>
__device__ __forceinline__ void gemm_body(
    const __half* __restrict__ Ah, const __half* __restrict__ Al,
    const __half* __restrict__ Bh, const __half* __restrict__ Bl,
    float* __restrict__ C, __half* __restrict__ Ch,
    __half* __restrict__ Cl, char* smem) {
    const uint32_t sb = smem_u32(smem);
    const int tid = threadIdx.x;
    const int lane = tid & 31;
    const int wid = tid >> 5;
    const int warp_m = wid & 3;
    const int warp_n = wid >> 2;
    const int row0 = blockIdx.y * 128;
    const int col0 = blockIdx.x * 64;

    const uint4* gA[2] = {reinterpret_cast<const uint4*>(Ah + (size_t)row0 * DIM),
                          reinterpret_cast<const uint4*>(Al + (size_t)row0 * DIM)};
    const uint4* gB[2] = {reinterpret_cast<const uint4*>(Bh + (size_t)col0 * DIM),
                          reinterpret_cast<const uint4*>(Bl + (size_t)col0 * DIM)};

    const int lrow = tid >> 3, lcol = tid & 7;

    auto load_stage = [&](int cidx, int s) {
        const int k0u = cidx * 8;
        const uint32_t sbase = sb + s * ST_SZ;
#pragma unroll
        for (int m = 0; m < 2; m++) {
#pragma unroll
            for (int r4 = 0; r4 < 4; r4++) {
                int row = lrow + r4 * 32;
                uint32_t off = SWZ128(row * 128 + lcol * 16);
                cp16(sbase + (m ? ST_AL : 0) + off, gA[m] + row * 128 + k0u + lcol);
            }
#pragma unroll
            for (int r4 = 0; r4 < 2; r4++) {
                int row = lrow + r4 * 32;
                uint32_t off = SWZ128(row * 128 + lcol * 16);
                cp16(sbase + (m ? ST_BL : ST_BH) + off, gB[m] + row * 128 + k0u + lcol);
            }
        }
        CP_COMMIT();
    };

    int amask[2], abase[2];
#pragma unroll
    for (int i = 0; i < 2; i++) {
        int r = warp_m * 32 + i * 16 + (lane & 15);
        amask[i] = (r & 7) << 4;
        abase[i] = r * 128 + ((lane >> 4) & 1) * 16;
    }
    // B fragments via ldsm_x4 (pair of n8 tiles per instruction; FA-proven pattern)
    const int bRow = ((lane >> 4) & 1) * 8 + (lane & 7);
    const int bHalf = ((lane >> 3) & 1) * 16;

    float acc[2][4][4] = {};

    load_stage(0, 0);
    CP_WAIT0();
    __syncthreads();

    for (int c = 0; c < 16; c++) {
        if (c < 15) load_stage(c + 1, (c + 1) & 1);
        const uint32_t sbase = sb + (c & 1) * ST_SZ;
#pragma unroll
        for (int ks = 0; ks < 4; ks++) {
            uint32_t ah[2][4], al[2][4], bh[4][2], bl[4][2];
#pragma unroll
            for (int i = 0; i < 2; i++) {
                uint32_t offA = (abase[i] + ks * 32) ^ amask[i];
                ldsm_x4(ah[i], sbase + offA);
                ldsm_x4(al[i], sbase + ST_AL + offA);
            }
#pragma unroll
            for (int jp = 0; jp < 2; jp++) {
                int r = warp_n * 32 + jp * 16 + bRow;
                uint32_t offB = SWZ128(r * 128 + ks * 32 + bHalf);
                ldsm_x4(&bh[2 * jp][0], sbase + ST_BH + offB);
                ldsm_x4(&bl[2 * jp][0], sbase + ST_BL + offB);
            }
#pragma unroll
            for (int i = 0; i < 2; i++)
#pragma unroll
                for (int j = 0; j < 4; j++)
                    mma_f16(acc[i][j], ah[i], bh[j]);
#pragma unroll
            for (int i = 0; i < 2; i++)
#pragma unroll
                for (int j = 0; j < 4; j++)
                    mma_f16(acc[i][j], ah[i], bl[j]);
#pragma unroll
            for (int i = 0; i < 2; i++)
#pragma unroll
                for (int j = 0; j < 4; j++)
                    mma_f16(acc[i][j], al[i], bh[j]);
        }
        if (c < 15) {
            CP_WAIT0();
            __syncthreads();
        }
    }

    const int fr = lane >> 2, fc = (lane & 3) * 2;
#pragma unroll
    for (int i = 0; i < 2; i++) {
        int rbase = row0 + warp_m * 32 + i * 16 + fr;
#pragma unroll
        for (int j = 0; j < 4; j++) {
            int col = col0 + warp_n * 32 + j * 8 + fc;
            if (SPLIT) {
                uint32_t h01, l01;
                hsplit2(acc[i][j][0], acc[i][j][1], h01, l01);
                *reinterpret_cast<uint32_t*>(&Ch[(size_t)rbase * DIM + col]) = h01;
                *reinterpret_cast<uint32_t*>(&Cl[(size_t)rbase * DIM + col]) = l01;
                hsplit2(acc[i][j][2], acc[i][j][3], h01, l01);
                *reinterpret_cast<uint32_t*>(&Ch[(size_t)(rbase + 8) * DIM + col]) = h01;
                *reinterpret_cast<uint32_t*>(&Cl[(size_t)(rbase + 8) * DIM + col]) = l01;
            } else {
                *reinterpret_cast<float2*>(&C[(size_t)rbase * DIM + col]) =
                    make_float2(acc[i][j][0], acc[i][j][1]);
                *reinterpret_cast<float2*>(&C[(size_t)(rbase + 8) * DIM + col]) =
                    make_float2(acc[i][j][2], acc[i][j][3]);
            }
        }
    }
}

struct QKVArgs {
    const __half* bh[3];
    const __half* bl[3];
    __half* ch[3];
    __half* cl[3];
};

__global__ __launch_bounds__(256, 2) void gemm_qkv(
    const __half* __restrict__ Ah, const __half* __restrict__ Al,
    QKVArgs args) {
    extern __shared__ char smem[];
    const int z = blockIdx.z;
    gemm_body<true>(Ah, Al, args.bh[z], args.bl[z], nullptr,
                    args.ch[z], args.cl[z], smem);
}

__global__ __launch_bounds__(256, 2) void gemm_wo(
    const __half* __restrict__ Ah, const __half* __restrict__ Al,
    const __half* __restrict__ Bh, const __half* __restrict__ Bl,
    float* __restrict__ C) {
    extern __shared__ char smem[];
    gemm_body<false>(Ah, Al, Bh, Bl, C, nullptr, nullptr, smem);
}

// ---------------- flash attention (fp16; QK x3 in exp2 domain, PV x1) --------
#define FA_QL 16384
#define FA_KV0 32768
#define FA_KVS 24576
#define FA_KL_O 8192
#define FA_VH_O 16384
#define FA_TOTAL (32768 + 2*24576)   // 81920

__global__ __launch_bounds__(256, 2) void flash_attn_mma(
    const __half* __restrict__ Qh, const __half* __restrict__ Ql,
    const __half* __restrict__ Kh, const __half* __restrict__ Kl,
    const __half* __restrict__ Vh,
    __half* __restrict__ Oh, __half* __restrict__ Ol) {
    extern __shared__ char smem[];
    const uint32_t sb = smem_u32(smem);
    const int tid = threadIdx.x, lane = tid & 31, wid = tid >> 5;
    const int qt = blockIdx.x, bhid = blockIdx.y;
    const int b = bhid >> 4, h = bhid & 15;
    const size_t base = ((size_t)(b * SEQ) * HEADS + h) * DHEAD;
    const uint4* Qhp = reinterpret_cast<const uint4*>(Qh + base);
    const uint4* Qlp = reinterpret_cast<const uint4*>(Ql + base);
    const uint4* Khp = reinterpret_cast<const uint4*>(Kh + base);
    const uint4* Klp = reinterpret_cast<const uint4*>(Kl + base);
    const uint4* Vhp = reinterpret_cast<const uint4*>(Vh + base);

    const int lrw = tid >> 3, lcl = tid & 7;

    auto load_kv = [&](int jt, int s) {
        const uint32_t kvb = sb + FA_KV0 + s * FA_KVS;
#pragma unroll
        for (int r4 = 0; r4 < 2; r4++) {
            int row = lrw + r4 * 32;
            uint32_t off = SWZ128(row * 128 + lcl * 16);
            int g = (jt * 64 + row) * 128 + lcl;
            cp16(kvb + off, Khp + g);
            cp16(kvb + FA_KL_O + off, Klp + g);
            cp16(kvb + FA_VH_O + off, Vhp + g);
        }
        CP_COMMIT();
    };

    load_kv(0, 0);
#pragma unroll
    for (int r4 = 0; r4 < 4; r4++) {
        int row = lrw + r4 * 32;
        uint32_t off = SWZ128(row * 128 + lcl * 16);
        int g = (qt * 128 + row) * 128 + lcl;
        *reinterpret_cast<uint4*>(smem + off) = Qhp[g];
        *reinterpret_cast<uint4*>(smem + FA_QL + off) = Qlp[g];
    }

    float m0 = -1e30f, m1 = -1e30f, l0 = 0.f, l1 = 0.f;
    float o[8][4] = {};
    const int fr = lane >> 2, fc = (lane & 3) * 2;
    const int qrow = wid * 16;
    const int aRow = lane & 15, aCol = (lane >> 4) * 16;
    const int kRow = ((lane >> 4) & 1) * 8 + (lane & 7);
    const int kHalf = ((lane >> 3) & 1) * 16;
    const int vRow = lane & 15;
    const int vColOff = ((lane >> 4) & 1) * 8;

    CP_WAIT0();
    __syncthreads();

    for (int jt = 0; jt < SEQ / 64; jt++) {
        const uint32_t kvb = sb + FA_KV0 + (jt & 1) * FA_KVS;
        if (jt + 1 < SEQ / 64) load_kv(jt + 1, (jt + 1) & 1);

        // ---- S = Q K^T (fp16 x3), exp2 domain ----
        float s[8][4] = {};
#pragma unroll
        for (int ks = 0; ks < 4; ks++) {
            uint32_t ah[4], al[4];
            uint32_t offA = SWZ128((qrow + aRow) * 128 + ks * 32 + aCol);
            ldsm_x4(ah, sb + offA);
            ldsm_x4(al, sb + FA_QL + offA);
#pragma unroll
            for (int jp = 0; jp < 2; jp++) {
                uint32_t kh4[2][4], kl4[2][4];
#pragma unroll
                for (int u = 0; u < 2; u++) {
                    int jj = jp * 2 + u;
                    uint32_t offB = SWZ128((jj * 16 + kRow) * 128 + ks * 32 + kHalf);
                    ldsm_x4(kh4[u], kvb + offB);
                    ldsm_x4(kl4[u], kvb + FA_KL_O + offB);
                }
#pragma unroll
                for (int u = 0; u < 2; u++) {
                    int jj = jp * 2 + u;
                    mma_f16(s[2 * jj], ah, kh4[u]);
                    mma_f16(s[2 * jj + 1], ah, kh4[u] + 2);
                }
#pragma unroll
                for (int u = 0; u < 2; u++) {
                    int jj = jp * 2 + u;
                    mma_f16(s[2 * jj], ah, kl4[u]);
                    mma_f16(s[2 * jj + 1], ah, kl4[u] + 2);
                }
#pragma unroll
                for (int u = 0; u < 2; u++) {
                    int jj = jp * 2 + u;
                    mma_f16(s[2 * jj], al, kh4[u]);
                    mma_f16(s[2 * jj + 1], al, kh4[u] + 2);
                }
            }
        }

        // ---- warp-local row max ----
        float rm0 = s[0][0], rm1 = s[0][2];
#pragma unroll
        for (int j = 0; j < 8; j++) {
            rm0 = fmaxf(rm0, fmaxf(s[j][0], s[j][1]));
            rm1 = fmaxf(rm1, fmaxf(s[j][2], s[j][3]));
        }
        rm0 = fmaxf(rm0, __shfl_xor_sync(0xffffffffu, rm0, 1));
        rm0 = fmaxf(rm0, __shfl_xor_sync(0xffffffffu, rm0, 2));
        rm1 = fmaxf(rm1, __shfl_xor_sync(0xffffffffu, rm1, 1));
        rm1 = fmaxf(rm1, __shfl_xor_sync(0xffffffffu, rm1, 2));
        float mn0 = fmaxf(m0, rm0), mn1 = fmaxf(m1, rm1);
        float a0 = ex2(m0 - mn0), a1 = ex2(m1 - mn1);
        m0 = mn0; m1 = mn1;

#pragma unroll
        for (int j = 0; j < 8; j++) {
            o[j][0] *= a0; o[j][1] *= a0;
            o[j][2] *= a1; o[j][3] *= a1;
        }

        // ---- PV x1 with fused exp2/pack ----
        float rs0 = 0.f, rs1 = 0.f;
#pragma unroll
        for (int kt = 0; kt < 4; kt++) {
            uint32_t pA[4];
#pragma unroll
            for (int u = 0; u < 2; u++) {
                int j = 2 * kt + u;
                float p0 = ex2(s[j][0] - mn0);
                float p1 = ex2(s[j][1] - mn0);
                float p2 = ex2(s[j][2] - mn1);
                float p3 = ex2(s[j][3] - mn1);
                rs0 += p0 + p1; rs1 += p2 + p3;
                __half2 t01 = __floats2half2_rn(p0, p1);
                __half2 t23 = __floats2half2_rn(p2, p3);
                pA[2 * u] = *reinterpret_cast<uint32_t*>(&t01);
                pA[2 * u + 1] = *reinterpret_cast<uint32_t*>(&t23);
            }
#pragma unroll
            for (int jj = 0; jj < 4; jj++) {
                uint32_t vh4[4];
                uint32_t offV = SWZ128((kt * 16 + vRow) * 128 + (jj * 16 + vColOff) * 2);
                ldsm_x4t(vh4, kvb + FA_VH_O + offV);
                mma_f16(o[2 * jj], pA, vh4);
                mma_f16(o[2 * jj + 1], pA, vh4 + 2);
            }
        }
        rs0 += __shfl_xor_sync(0xffffffffu, rs0, 1);
        rs0 += __shfl_xor_sync(0xffffffffu, rs0, 2);
        rs1 += __shfl_xor_sync(0xffffffffu, rs1, 1);
        rs1 += __shfl_xor_sync(0xffffffffu, rs1, 2);
        l0 = l0 * a0 + rs0;
        l1 = l1 * a1 + rs1;

        if (jt + 1 < SEQ / 64) CP_WAIT0();
        __syncthreads();
    }

    // ---- epilogue: normalize, split, store [b,n,h,e] ----
    float inv0 = 1.f / l0, inv1 = 1.f / l1;
    const int r0g = qt * 128 + qrow + fr;
#pragma unroll
    for (int j = 0; j < 8; j++) {
        int col = j * 8 + fc;
        uint32_t h01, l01;
        hsplit2(o[j][0] * inv0, o[j][1] * inv0, h01, l01);
        *reinterpret_cast<uint32_t*>(Oh + base + (size_t)r0g * 1024 + col) = h01;
        *reinterpret_cast<uint32_t*>(Ol + base + (size_t)r0g * 1024 + col) = l01;
        hsplit2(o[j][2] * inv1, o[j][3] * inv1, h01, l01);
        *reinterpret_cast<uint32_t*>(Oh + base + (size_t)(r0g + 8) * 1024 + col) = h01;
        *reinterpret_cast<uint32_t*>(Ol + base + (size_t)(r0g + 8) * 1024 + col) = l01;
    }
}

// ---------------- launch ------------------------------------------------------
extern "C" void kernel_launch(void* const* d_in, const int* in_sizes, int n_in,
                              void* d_out, int out_size) {
    const float* tokens = (const float*)d_in[0];
    const float* wq = (const float*)d_in[1];
    const float* wk = (const float*)d_in[2];
    const float* wv = (const float*)d_in[3];
    const float* wo = (const float*)d_in[4];
    float* out = (float*)d_out;

    __half *tokh, *tokl, *qh, *ql, *kh, *kl, *vh, *vl, *aggh, *aggl;
    __half *wqh, *wql, *wkh, *wkl, *wvh, *wvl, *woh, *wol;
    cudaGetSymbolAddress((void**)&tokh, g_tokh);
    cudaGetSymbolAddress((void**)&tokl, g_tokl);
    cudaGetSymbolAddress((void**)&qh, g_qh);
    cudaGetSymbolAddress((void**)&ql, g_ql);
    cudaGetSymbolAddress((void**)&kh, g_kh);
    cudaGetSymbolAddress((void**)&kl, g_kl);
    cudaGetSymbolAddress((void**)&vh, g_vh);
    cudaGetSymbolAddress((void**)&vl, g_vl);
    cudaGetSymbolAddress((void**)&aggh, g_aggh);
    cudaGetSymbolAddress((void**)&aggl, g_aggl);
    cudaGetSymbolAddress((void**)&wqh, g_wqh);
    cudaGetSymbolAddress((void**)&wql, g_wql);
    cudaGetSymbolAddress((void**)&wkh, g_wkh);
    cudaGetSymbolAddress((void**)&wkl, g_wkl);
    cudaGetSymbolAddress((void**)&wvh, g_wvh);
    cudaGetSymbolAddress((void**)&wvl, g_wvl);
    cudaGetSymbolAddress((void**)&woh, g_woh);
    cudaGetSymbolAddress((void**)&wol, g_wol);

    prep_all<<<8192, 256>>>((const float4*)tokens, wq, wk, wv, wo);

    cudaFuncSetAttribute(gemm_qkv, cudaFuncAttributeMaxDynamicSharedMemorySize,
                         GS2_TOTAL);
    cudaFuncSetAttribute(gemm_wo, cudaFuncAttributeMaxDynamicSharedMemorySize,
                         GS2_TOTAL);

    QKVArgs args;
    args.bh[0] = wqh; args.bl[0] = wql; args.ch[0] = qh; args.cl[0] = ql;
    args.bh[1] = wkh; args.bl[1] = wkl; args.ch[1] = kh; args.cl[1] = kl;
    args.bh[2] = wvh; args.bl[2] = wvl; args.ch[2] = vh; args.cl[2] = vl;

    dim3 gqkv(DIM / 64, BS / 128, 3);
    gemm_qkv<<<gqkv, 256, GS2_TOTAL>>>(tokh, tokl, args);

    cudaFuncSetAttribute(flash_attn_mma,
                         cudaFuncAttributeMaxDynamicSharedMemorySize, FA_TOTAL);
    flash_attn_mma<<<dim3(SEQ / 128, BATCH * HEADS), 256, FA_TOTAL>>>(
        qh, ql, kh, kl, vh, aggh, aggl);

    dim3 gp(DIM / 64, BS / 128);
    gemm_wo<<<gp, 256, GS2_TOTAL>>>(aggh, aggl, woh, wol, out);
}

// round 15
// speedup vs baseline: 1.7565x; 1.1088x over previous
#include <cuda_runtime.h>
#include <cuda_fp16.h>
#include <cstdint>

#define BATCH 2
#define SEQ 2048
#define DIM 1024
#define HEADS 16
#define DHEAD 64
#define BS (BATCH*SEQ)   // 4096

// ---------------- scratch (device globals; no allocations allowed) ----------
__device__ __half g_tokh[BS*DIM], g_tokl[BS*DIM];
__device__ __half g_qh[BS*DIM], g_ql[BS*DIM];
__device__ __half g_kh[BS*DIM], g_kl[BS*DIM];
__device__ __half g_vh[BS*DIM], g_vl[BS*DIM];
__device__ __half g_aggh[BS*DIM], g_aggl[BS*DIM];
__device__ __half g_wqh[DIM*DIM], g_wql[DIM*DIM];
__device__ __half g_wkh[DIM*DIM], g_wkl[DIM*DIM];
__device__ __half g_wvh[DIM*DIM], g_wvl[DIM*DIM];
__device__ __half g_woh[DIM*DIM], g_wol[DIM*DIM];

// ---------------- helpers ----------------------------------------------------
__device__ __forceinline__ uint32_t smem_u32(const void* p) {
    uint32_t a;
    asm("{ .reg .u64 t; cvta.to.shared.u64 t, %1; cvt.u32.u64 %0, t; }"
        : "=r"(a) : "l"(p));
    return a;
}
#define SWZ128(o) ((o) ^ (((o) >> 3) & 0x70))

__device__ __forceinline__ void cp16(uint32_t saddr, const void* gptr) {
    asm volatile("cp.async.cg.shared.global [%0], [%1], 16;"
                 :: "r"(saddr), "l"(gptr));
}
#define CP_COMMIT() asm volatile("cp.async.commit_group;" ::: "memory")
#define CP_WAIT0()  asm volatile("cp.async.wait_group 0;" ::: "memory")

__device__ __forceinline__ void ldsm_x4(uint32_t* r, uint32_t addr) {
    asm volatile("ldmatrix.sync.aligned.m8n8.x4.shared.b16 {%0,%1,%2,%3}, [%4];"
                 : "=r"(r[0]), "=r"(r[1]), "=r"(r[2]), "=r"(r[3]) : "r"(addr));
}
__device__ __forceinline__ void ldsm_x4t(uint32_t* r, uint32_t addr) {
    asm volatile("ldmatrix.sync.aligned.m8n8.x4.trans.shared.b16 {%0,%1,%2,%3}, [%4];"
                 : "=r"(r[0]), "=r"(r[1]), "=r"(r[2]), "=r"(r[3]) : "r"(addr));
}
__device__ __forceinline__ void mma_f16(float* c, const uint32_t* a, const uint32_t* b) {
    asm volatile(
        "mma.sync.aligned.m16n8k16.row.col.f32.f16.f16.f32 "
        "{%0,%1,%2,%3}, {%4,%5,%6,%7}, {%8,%9}, {%0,%1,%2,%3};"
        : "+f"(c[0]), "+f"(c[1]), "+f"(c[2]), "+f"(c[3])
        : "r"(a[0]), "r"(a[1]), "r"(a[2]), "r"(a[3]), "r"(b[0]), "r"(b[1]));
}
__device__ __forceinline__ float ex2(float x) {
    float y;
    asm("ex2.approx.ftz.f32 %0, %1;" : "=f"(y) : "f"(x));
    return y;
}
__device__ __forceinline__ void hsplit(float v, __half& h, __half& l) {
    h = __float2half_rn(v);
    l = __float2half_rn(v - __half2float(h));
}
__device__ __forceinline__ void hsplit2(float a, float b, uint32_t& hi, uint32_t& lo) {
    __half2 h = __floats2half2_rn(a, b);
    float2 f = __half22float2(h);
    __half2 l = __floats2half2_rn(a - f.x, b - f.y);
    hi = *reinterpret_cast<uint32_t*>(&h);
    lo = *reinterpret_cast<uint32_t*>(&l);
}

// ---------------- fused prep: token split + coalesced weight transpose ------
#define QSCALE 0.18033688011112042f   // 0.125 * log2(e)

__global__ void prep_all(const float4* __restrict__ tok,
                         const float* __restrict__ wq, const float* __restrict__ wk,
                         const float* __restrict__ wv, const float* __restrict__ wo) {
    __shared__ float tile[32][33];
    const int blk = blockIdx.x;
    const int tid = threadIdx.x;

    if (blk < 4096) {
        int i = blk * 256 + tid;
        float4 v = tok[i];
        uint32_t h01, l01, h23, l23;
        hsplit2(v.x, v.y, h01, l01);
        hsplit2(v.z, v.w, h23, l23);
        uint32_t* H = reinterpret_cast<uint32_t*>(g_tokh);
        uint32_t* L = reinterpret_cast<uint32_t*>(g_tokl);
        H[2 * i] = h01; H[2 * i + 1] = h23;
        L[2 * i] = l01; L[2 * i + 1] = l23;
        return;
    }

    const int wb = blk - 4096;
    if (wb < 3072) {
        const int arr = wb >> 10;
        const int t = wb & 1023;
        const int h = t >> 6;
        const int tt = t & 63;
        const int d0 = (tt >> 1) * 32;
        const int e0 = (tt & 1) * 32;
        const float* src = (arr == 0 ? wq : arr == 1 ? wk : wv) + (size_t)h * DIM * DHEAD;
        __half* dh = (arr == 0 ? g_wqh : arr == 1 ? g_wkh : g_wvh);
        __half* dl = (arr == 0 ? g_wql : arr == 1 ? g_wkl : g_wvl);
        const float scale = (arr == 0) ? QSCALE : 1.0f;

#pragma unroll
        for (int p = 0; p < 4; p++) {
            int lin = p * 256 + tid;
            int r = lin >> 5, c = lin & 31;
            tile[r][c] = src[(size_t)(d0 + r) * DHEAD + e0 + c] * scale;
        }
        __syncthreads();
#pragma unroll
        for (int p = 0; p < 4; p++) {
            int lin = p * 256 + tid;
            int rr = lin >> 5, cc = lin & 31;
            int n = h * 64 + e0 + rr;
            int k = d0 + cc;
            __half hh, ll;
            hsplit(tile[cc][rr], hh, ll);
            dh[(size_t)n * DIM + k] = hh;
            dl[(size_t)n * DIM + k] = ll;
        }
    } else {
        const int t2 = wb - 3072;
        const int he0 = (t2 >> 5) * 32;
        const int d0 = (t2 & 31) * 32;
#pragma unroll
        for (int p = 0; p < 4; p++) {
            int lin = p * 256 + tid;
            int r = lin >> 5, c = lin & 31;
            tile[r][c] = wo[(size_t)(he0 + r) * DIM + d0 + c];
        }
        __syncthreads();
#pragma unroll
        for (int p = 0; p < 4; p++) {
            int lin = p * 256 + tid;
            int rr = lin >> 5, cc = lin & 31;
            int n = d0 + rr;
            int k = he0 + cc;
            __half hh, ll;
            hsplit(tile[cc][rr], hh, ll);
            g_woh[(size_t)n * DIM + k] = hh;
            g_wol[(size_t)n * DIM + k] = ll;
        }
    }
}

// ---------------- fp16x3 GEMM (HMMA + cp.async 2-stage) -----------------------
// three=false (v projection): skip al*bh MMA group (loads unchanged).
#define ST_AL 16384
#define ST_BH 32768
#define ST_BL 40960
#define ST_SZ 49152
#define GS2_TOTAL (2*ST_SZ)

__device__ __forceinline__ void gemm_split_body(
    const __half* __restrict__ Ah, const __half* __restrict__ Al,
    const __half* __restrict__ Bh, const __half* __restrict__ Bl,
    __half* __restrict__ Ch, __half* __restrict__ Cl,
    bool three, char* smem) {
    const uint32_t sb = smem_u32(smem);
    const int tid = threadIdx.x;
    const int lane = tid & 31;
    const int wid = tid >> 5;
    const int warp_m = wid & 3;
    const int warp_n = wid >> 2;
    const int row0 = blockIdx.y * 128;
    const int col0 = blockIdx.x * 64;

    const uint4* gA[2] = {reinterpret_cast<const uint4*>(Ah + (size_t)row0 * DIM),
                          reinterpret_cast<const uint4*>(Al + (size_t)row0 * DIM)};
    const uint4* gB[2] = {reinterpret_cast<const uint4*>(Bh + (size_t)col0 * DIM),
                          reinterpret_cast<const uint4*>(Bl + (size_t)col0 * DIM)};

    const int lrow = tid >> 3, lcol = tid & 7;

    auto load_stage = [&](int cidx, int s) {
        const int k0u = cidx * 8;
        const uint32_t sbase = sb + s * ST_SZ;
#pragma unroll
        for (int m = 0; m < 2; m++) {
#pragma unroll
            for (int r4 = 0; r4 < 4; r4++) {
                int row = lrow + r4 * 32;
                uint32_t off = SWZ128(row * 128 + lcol * 16);
                cp16(sbase + (m ? ST_AL : 0) + off, gA[m] + row * 128 + k0u + lcol);
            }
#pragma unroll
            for (int r4 = 0; r4 < 2; r4++) {
                int row = lrow + r4 * 32;
                uint32_t off = SWZ128(row * 128 + lcol * 16);
                cp16(sbase + (m ? ST_BL : ST_BH) + off, gB[m] + row * 128 + k0u + lcol);
            }
        }
        CP_COMMIT();
    };

    int amask[2], abase[2];
#pragma unroll
    for (int i = 0; i < 2; i++) {
        int r = warp_m * 32 + i * 16 + (lane & 15);
        amask[i] = (r & 7) << 4;
        abase[i] = r * 128 + ((lane >> 4) & 1) * 16;
    }
    const int bRow = ((lane >> 4) & 1) * 8 + (lane & 7);
    const int bHalf = ((lane >> 3) & 1) * 16;

    float acc[2][4][4] = {};

    load_stage(0, 0);
    CP_WAIT0();
    __syncthreads();

    for (int c = 0; c < 16; c++) {
        if (c < 15) load_stage(c + 1, (c + 1) & 1);
        const uint32_t sbase = sb + (c & 1) * ST_SZ;
#pragma unroll
        for (int ks = 0; ks < 4; ks++) {
            uint32_t ah[2][4], al[2][4], bh[4][2], bl[4][2];
#pragma unroll
            for (int i = 0; i < 2; i++) {
                uint32_t offA = (abase[i] + ks * 32) ^ amask[i];
                ldsm_x4(ah[i], sbase + offA);
                ldsm_x4(al[i], sbase + ST_AL + offA);
            }
#pragma unroll
            for (int jp = 0; jp < 2; jp++) {
                int r = warp_n * 32 + jp * 16 + bRow;
                uint32_t offB = SWZ128(r * 128 + ks * 32 + bHalf);
                ldsm_x4(&bh[2 * jp][0], sbase + ST_BH + offB);
                ldsm_x4(&bl[2 * jp][0], sbase + ST_BL + offB);
            }
#pragma unroll
            for (int i = 0; i < 2; i++)
#pragma unroll
                for (int j = 0; j < 4; j++)
                    mma_f16(acc[i][j], ah[i], bh[j]);
#pragma unroll
            for (int i = 0; i < 2; i++)
#pragma unroll
                for (int j = 0; j < 4; j++)
                    mma_f16(acc[i][j], ah[i], bl[j]);
            if (three) {
#pragma unroll
                for (int i = 0; i < 2; i++)
#pragma unroll
                    for (int j = 0; j < 4; j++)
                        mma_f16(acc[i][j], al[i], bh[j]);
            }
        }
        if (c < 15) {
            CP_WAIT0();
            __syncthreads();
        }
    }

    const int fr = lane >> 2, fc = (lane & 3) * 2;
#pragma unroll
    for (int i = 0; i < 2; i++) {
        int rbase = row0 + warp_m * 32 + i * 16 + fr;
#pragma unroll
        for (int j = 0; j < 4; j++) {
            int col = col0 + warp_n * 32 + j * 8 + fc;
            uint32_t h01, l01;
            hsplit2(acc[i][j][0], acc[i][j][1], h01, l01);
            *reinterpret_cast<uint32_t*>(&Ch[(size_t)rbase * DIM + col]) = h01;
            *reinterpret_cast<uint32_t*>(&Cl[(size_t)rbase * DIM + col]) = l01;
            hsplit2(acc[i][j][2], acc[i][j][3], h01, l01);
            *reinterpret_cast<uint32_t*>(&Ch[(size_t)(rbase + 8) * DIM + col]) = h01;
            *reinterpret_cast<uint32_t*>(&Cl[(size_t)(rbase + 8) * DIM + col]) = l01;
        }
    }
}

struct QKVArgs {
    const __half* bh[3];
    const __half* bl[3];
    __half* ch[3];
    __half* cl[3];
};

__global__ __launch_bounds__(256, 2) void gemm_qkv(
    const __half* __restrict__ Ah, const __half* __restrict__ Al,
    QKVArgs args) {
    extern __shared__ char smem[];
    const int z = blockIdx.z;
    gemm_split_body(Ah, Al, args.bh[z], args.bl[z],
                    args.ch[z], args.cl[z], z != 2, smem);
}

// ---------------- fp16x2 GEMM for wo: C = Ah * (Bh + Bl)^T, fp32 out ---------
// stage: AH 16K | BH 8K | BL 8K = 32K; 2 stages = 64K
#define W2_BH 16384
#define W2_BL 24576
#define W2_SZ 32768
#define GW2_TOTAL (2*W2_SZ)

__global__ __launch_bounds__(256, 2) void gemm_wo_x2(
    const __half* __restrict__ Ah,
    const __half* __restrict__ Bh, const __half* __restrict__ Bl,
    float* __restrict__ C) {
    extern __shared__ char smem[];
    const uint32_t sb = smem_u32(smem);
    const int tid = threadIdx.x;
    const int lane = tid & 31;
    const int wid = tid >> 5;
    const int warp_m = wid & 3;
    const int warp_n = wid >> 2;
    const int row0 = blockIdx.y * 128;
    const int col0 = blockIdx.x * 64;

    const uint4* gA = reinterpret_cast<const uint4*>(Ah + (size_t)row0 * DIM);
    const uint4* gB[2] = {reinterpret_cast<const uint4*>(Bh + (size_t)col0 * DIM),
                          reinterpret_cast<const uint4*>(Bl + (size_t)col0 * DIM)};

    const int lrow = tid >> 3, lcol = tid & 7;

    auto load_stage = [&](int cidx, int s) {
        const int k0u = cidx * 8;
        const uint32_t sbase = sb + s * W2_SZ;
#pragma unroll
        for (int r4 = 0; r4 < 4; r4++) {
            int row = lrow + r4 * 32;
            uint32_t off = SWZ128(row * 128 + lcol * 16);
            cp16(sbase + off, gA + row * 128 + k0u + lcol);
        }
#pragma unroll
        for (int m = 0; m < 2; m++) {
#pragma unroll
            for (int r4 = 0; r4 < 2; r4++) {
                int row = lrow + r4 * 32;
                uint32_t off = SWZ128(row * 128 + lcol * 16);
                cp16(sbase + (m ? W2_BL : W2_BH) + off, gB[m] + row * 128 + k0u + lcol);
            }
        }
        CP_COMMIT();
    };

    int amask[2], abase[2];
#pragma unroll
    for (int i = 0; i < 2; i++) {
        int r = warp_m * 32 + i * 16 + (lane & 15);
        amask[i] = (r & 7) << 4;
        abase[i] = r * 128 + ((lane >> 4) & 1) * 16;
    }
    const int bRow = ((lane >> 4) & 1) * 8 + (lane & 7);
    const int bHalf = ((lane >> 3) & 1) * 16;

    float acc[2][4][4] = {};

    load_stage(0, 0);
    CP_WAIT0();
    __syncthreads();

    for (int c = 0; c < 16; c++) {
        if (c < 15) load_stage(c + 1, (c + 1) & 1);
        const uint32_t sbase = sb + (c & 1) * W2_SZ;
#pragma unroll
        for (int ks = 0; ks < 4; ks++) {
            uint32_t ah[2][4], bh[4][2], bl[4][2];
#pragma unroll
            for (int i = 0; i < 2; i++) {
                uint32_t offA = (abase[i] + ks * 32) ^ amask[i];
                ldsm_x4(ah[i], sbase + offA);
            }
#pragma unroll
            for (int jp = 0; jp < 2; jp++) {
                int r = warp_n * 32 + jp * 16 + bRow;
                uint32_t offB = SWZ128(r * 128 + ks * 32 + bHalf);
                ldsm_x4(&bh[2 * jp][0], sbase + W2_BH + offB);
                ldsm_x4(&bl[2 * jp][0], sbase + W2_BL + offB);
            }
#pragma unroll
            for (int i = 0; i < 2; i++)
#pragma unroll
                for (int j = 0; j < 4; j++)
                    mma_f16(acc[i][j], ah[i], bh[j]);
#pragma unroll
            for (int i = 0; i < 2; i++)
#pragma unroll
                for (int j = 0; j < 4; j++)
                    mma_f16(acc[i][j], ah[i], bl[j]);
        }
        if (c < 15) {
            CP_WAIT0();
            __syncthreads();
        }
    }

    const int fr = lane >> 2, fc = (lane & 3) * 2;
#pragma unroll
    for (int i = 0; i < 2; i++) {
        int rbase = row0 + warp_m * 32 + i * 16 + fr;
#pragma unroll
        for (int j = 0; j < 4; j++) {
            int col = col0 + warp_n * 32 + j * 8 + fc;
            *reinterpret_cast<float2*>(&C[(size_t)rbase * DIM + col]) =
                make_float2(acc[i][j][0], acc[i][j][1]);
            *reinterpret_cast<float2*>(&C[(size_t)(rbase + 8) * DIM + col]) =
                make_float2(acc[i][j][2], acc[i][j][3]);
        }
    }
}

// ---------------- flash attention (fp16; QK x3 in exp2 domain, PV x1) --------
#define FA_QL 16384
#define FA_KV0 32768
#define FA_KVS 24576
#define FA_KL_O 8192
#define FA_VH_O 16384
#define FA_TOTAL (32768 + 2*24576)   // 81920

__global__ __launch_bounds__(256, 2) void flash_attn_mma(
    const __half* __restrict__ Qh, const __half* __restrict__ Ql,
    const __half* __restrict__ Kh, const __half* __restrict__ Kl,
    const __half* __restrict__ Vh,
    __half* __restrict__ Oh, __half* __restrict__ Ol) {
    extern __shared__ char smem[];
    const uint32_t sb = smem_u32(smem);
    const int tid = threadIdx.x, lane = tid & 31, wid = tid >> 5;
    const int qt = blockIdx.x, bhid = blockIdx.y;
    const int b = bhid >> 4, h = bhid & 15;
    const size_t base = ((size_t)(b * SEQ) * HEADS + h) * DHEAD;
    const uint4* Qhp = reinterpret_cast<const uint4*>(Qh + base);
    const uint4* Qlp = reinterpret_cast<const uint4*>(Ql + base);
    const uint4* Khp = reinterpret_cast<const uint4*>(Kh + base);
    const uint4* Klp = reinterpret_cast<const uint4*>(Kl + base);
    const uint4* Vhp = reinterpret_cast<const uint4*>(Vh + base);

    const int lrw = tid >> 3, lcl = tid & 7;

    auto load_kv = [&](int jt, int s) {
        const uint32_t kvb = sb + FA_KV0 + s * FA_KVS;
#pragma unroll
        for (int r4 = 0; r4 < 2; r4++) {
            int row = lrw + r4 * 32;
            uint32_t off = SWZ128(row * 128 + lcl * 16);
            int g = (jt * 64 + row) * 128 + lcl;
            cp16(kvb + off, Khp + g);
            cp16(kvb + FA_KL_O + off, Klp + g);
            cp16(kvb + FA_VH_O + off, Vhp + g);
        }
        CP_COMMIT();
    };

    load_kv(0, 0);
#pragma unroll
    for (int r4 = 0; r4 < 4; r4++) {
        int row = lrw + r4 * 32;
        uint32_t off = SWZ128(row * 128 + lcl * 16);
        int g = (qt * 128 + row) * 128 + lcl;
        *reinterpret_cast<uint4*>(smem + off) = Qhp[g];
        *reinterpret_cast<uint4*>(smem + FA_QL + off) = Qlp[g];
    }

    float m0 = -1e30f, m1 = -1e30f, l0 = 0.f, l1 = 0.f;
    float o[8][4] = {};
    const int fr = lane >> 2, fc = (lane & 3) * 2;
    const int qrow = wid * 16;
    const int aRow = lane & 15, aCol = (lane >> 4) * 16;
    const int kRow = ((lane >> 4) & 1) * 8 + (lane & 7);
    const int kHalf = ((lane >> 3) & 1) * 16;
    const int vRow = lane & 15;
    const int vColOff = ((lane >> 4) & 1) * 8;

    CP_WAIT0();
    __syncthreads();

    for (int jt = 0; jt < SEQ / 64; jt++) {
        const uint32_t kvb = sb + FA_KV0 + (jt & 1) * FA_KVS;
        if (jt + 1 < SEQ / 64) load_kv(jt + 1, (jt + 1) & 1);

        // ---- S = Q K^T (fp16 x3), exp2 domain ----
        float s[8][4] = {};
#pragma unroll
        for (int ks = 0; ks < 4; ks++) {
            uint32_t ah[4], al[4];
            uint32_t offA = SWZ128((qrow + aRow) * 128 + ks * 32 + aCol);
            ldsm_x4(ah, sb + offA);
            ldsm_x4(al, sb + FA_QL + offA);
#pragma unroll
            for (int jp = 0; jp < 2; jp++) {
                uint32_t kh4[2][4], kl4[2][4];
#pragma unroll
                for (int u = 0; u < 2; u++) {
                    int jj = jp * 2 + u;
                    uint32_t offB = SWZ128((jj * 16 + kRow) * 128 + ks * 32 + kHalf);
                    ldsm_x4(kh4[u], kvb + offB);
                    ldsm_x4(kl4[u], kvb + FA_KL_O + offB);
                }
#pragma unroll
                for (int u = 0; u < 2; u++) {
                    int jj = jp * 2 + u;
                    mma_f16(s[2 * jj], ah, kh4[u]);
                    mma_f16(s[2 * jj + 1], ah, kh4[u] + 2);
                }
#pragma unroll
                for (int u = 0; u < 2; u++) {
                    int jj = jp * 2 + u;
                    mma_f16(s[2 * jj], ah, kl4[u]);
                    mma_f16(s[2 * jj + 1], ah, kl4[u] + 2);
                }
#pragma unroll
                for (int u = 0; u < 2; u++) {
                    int jj = jp * 2 + u;
                    mma_f16(s[2 * jj], al, kh4[u]);
                    mma_f16(s[2 * jj + 1], al, kh4[u] + 2);
                }
            }
        }

        // ---- warp-local row max ----
        float rm0 = s[0][0], rm1 = s[0][2];
#pragma unroll
        for (int j = 0; j < 8; j++) {
            rm0 = fmaxf(rm0, fmaxf(s[j][0], s[j][1]));
            rm1 = fmaxf(rm1, fmaxf(s[j][2], s[j][3]));
        }
        rm0 = fmaxf(rm0, __shfl_xor_sync(0xffffffffu, rm0, 1));
        rm0 = fmaxf(rm0, __shfl_xor_sync(0xffffffffu, rm0, 2));
        rm1 = fmaxf(rm1, __shfl_xor_sync(0xffffffffu, rm1, 1));
        rm1 = fmaxf(rm1, __shfl_xor_sync(0xffffffffu, rm1, 2));
        float mn0 = fmaxf(m0, rm0), mn1 = fmaxf(m1, rm1);
        float a0 = ex2(m0 - mn0), a1 = ex2(m1 - mn1);
        m0 = mn0; m1 = mn1;

#pragma unroll
        for (int j = 0; j < 8; j++) {
            o[j][0] *= a0; o[j][1] *= a0;
            o[j][2] *= a1; o[j][3] *= a1;
        }

        // ---- PV x1 with fused exp2/pack ----
        float rs0 = 0.f, rs1 = 0.f;
#pragma unroll
        for (int kt = 0; kt < 4; kt++) {
            uint32_t pA[4];
#pragma unroll
            for (int u = 0; u < 2; u++) {
                int j = 2 * kt + u;
                float p0 = ex2(s[j][0] - mn0);
                float p1 = ex2(s[j][1] - mn0);
                float p2 = ex2(s[j][2] - mn1);
                float p3 = ex2(s[j][3] - mn1);
                rs0 += p0 + p1; rs1 += p2 + p3;
                __half2 t01 = __floats2half2_rn(p0, p1);
                __half2 t23 = __floats2half2_rn(p2, p3);
                pA[2 * u] = *reinterpret_cast<uint32_t*>(&t01);
                pA[2 * u + 1] = *reinterpret_cast<uint32_t*>(&t23);
            }
#pragma unroll
            for (int jj = 0; jj < 4; jj++) {
                uint32_t vh4[4];
                uint32_t offV = SWZ128((kt * 16 + vRow) * 128 + (jj * 16 + vColOff) * 2);
                ldsm_x4t(vh4, kvb + FA_VH_O + offV);
                mma_f16(o[2 * jj], pA, vh4);
                mma_f16(o[2 * jj + 1], pA, vh4 + 2);
            }
        }
        rs0 += __shfl_xor_sync(0xffffffffu, rs0, 1);
        rs0 += __shfl_xor_sync(0xffffffffu, rs0, 2);
        rs1 += __shfl_xor_sync(0xffffffffu, rs1, 1);
        rs1 += __shfl_xor_sync(0xffffffffu, rs1, 2);
        l0 = l0 * a0 + rs0;
        l1 = l1 * a1 + rs1;

        if (jt + 1 < SEQ / 64) CP_WAIT0();
        __syncthreads();
    }

    // ---- epilogue: normalize, split, store [b,n,h,e] ----
    float inv0 = 1.f / l0, inv1 = 1.f / l1;
    const int r0g = qt * 128 + qrow + fr;
#pragma unroll
    for (int j = 0; j < 8; j++) {
        int col = j * 8 + fc;
        uint32_t h01, l01;
        hsplit2(o[j][0] * inv0, o[j][1] * inv0, h01, l01);
        *reinterpret_cast<uint32_t*>(Oh + base + (size_t)r0g * 1024 + col) = h01;
        *reinterpret_cast<uint32_t*>(Ol + base + (size_t)r0g * 1024 + col) = l01;
        hsplit2(o[j][2] * inv1, o[j][3] * inv1, h01, l01);
        *reinterpret_cast<uint32_t*>(Oh + base + (size_t)(r0g + 8) * 1024 + col) = h01;
        *reinterpret_cast<uint32_t*>(Ol + base + (size_t)(r0g + 8) * 1024 + col) = l01;
    }
}

// ---------------- launch ------------------------------------------------------
extern "C" void kernel_launch(void* const* d_in, const int* in_sizes, int n_in,
                              void* d_out, int out_size) {
    const float* tokens = (const float*)d_in[0];
    const float* wq = (const float*)d_in[1];
    const float* wk = (const float*)d_in[2];
    const float* wv = (const float*)d_in[3];
    const float* wo = (const float*)d_in[4];
    float* out = (float*)d_out;

    __half *tokh, *tokl, *qh, *ql, *kh, *kl, *vh, *vl, *aggh, *aggl;
    __half *wqh, *wql, *wkh, *wkl, *wvh, *wvl, *woh, *wol;
    cudaGetSymbolAddress((void**)&tokh, g_tokh);
    cudaGetSymbolAddress((void**)&tokl, g_tokl);
    cudaGetSymbolAddress((void**)&qh, g_qh);
    cudaGetSymbolAddress((void**)&ql, g_ql);
    cudaGetSymbolAddress((void**)&kh, g_kh);
    cudaGetSymbolAddress((void**)&kl, g_kl);
    cudaGetSymbolAddress((void**)&vh, g_vh);
    cudaGetSymbolAddress((void**)&vl, g_vl);
    cudaGetSymbolAddress((void**)&aggh, g_aggh);
    cudaGetSymbolAddress((void**)&aggl, g_aggl);
    cudaGetSymbolAddress((void**)&wqh, g_wqh);
    cudaGetSymbolAddress((void**)&wql, g_wql);
    cudaGetSymbolAddress((void**)&wkh, g_wkh);
    cudaGetSymbolAddress((void**)&wkl, g_wkl);
    cudaGetSymbolAddress((void**)&wvh, g_wvh);
    cudaGetSymbolAddress((void**)&wvl, g_wvl);
    cudaGetSymbolAddress((void**)&woh, g_woh);
    cudaGetSymbolAddress((void**)&wol, g_wol);

    prep_all<<<8192, 256>>>((const float4*)tokens, wq, wk, wv, wo);

    cudaFuncSetAttribute(gemm_qkv, cudaFuncAttributeMaxDynamicSharedMemorySize,
                         GS2_TOTAL);
    cudaFuncSetAttribute(gemm_wo_x2, cudaFuncAttributeMaxDynamicSharedMemorySize,
                         GW2_TOTAL);

    QKVArgs args;
    args.bh[0] = wqh; args.bl[0] = wql; args.ch[0] = qh; args.cl[0] = ql;
    args.bh[1] = wkh; args.bl[1] = wkl; args.ch[1] = kh; args.cl[1] = kl;
    args.bh[2] = wvh; args.bl[2] = wvl; args.ch[2] = vh; args.cl[2] = vl;

    dim3 gqkv(DIM / 64, BS / 128, 3);
    gemm_qkv<<<gqkv, 256, GS2_TOTAL>>>(tokh, tokl, args);

    cudaFuncSetAttribute(flash_attn_mma,
                         cudaFuncAttributeMaxDynamicSharedMemorySize, FA_TOTAL);
    flash_attn_mma<<<dim3(SEQ / 128, BATCH * HEADS), 256, FA_TOTAL>>>(
        qh, ql, kh, kl, vh, aggh, aggl);

    dim3 gp(DIM / 64, BS / 128);
    gemm_wo_x2<<<gp, 256, GW2_TOTAL>>>(aggh, woh, wol, out);
}

// round 16
// speedup vs baseline: 1.9463x; 1.1081x over previous
#include <cuda_runtime.h>
#include <cuda_fp16.h>
#include <cstdint>

#define BATCH 2
#define SEQ 2048
#define DIM 1024
#define HEADS 16
#define DHEAD 64
#define BS (BATCH*SEQ)   // 4096

// ---------------- scratch (device globals; no allocations allowed) ----------
__device__ __half g_tokh[BS*DIM], g_tokl[BS*DIM];
__device__ __half g_qh[BS*DIM], g_ql[BS*DIM];
__device__ __half g_kh[BS*DIM], g_kl[BS*DIM];
__device__ __half g_v[BS*DIM];
__device__ __half g_agg[BS*DIM];
__device__ __half g_wqh[DIM*DIM], g_wql[DIM*DIM];
__device__ __half g_wkh[DIM*DIM], g_wkl[DIM*DIM];
__device__ __half g_wvh[DIM*DIM];
__device__ __half g_woh[DIM*DIM];

// ---------------- helpers ----------------------------------------------------
__device__ __forceinline__ uint32_t smem_u32(const void* p) {
    uint32_t a;
    asm("{ .reg .u64 t; cvta.to.shared.u64 t, %1; cvt.u32.u64 %0, t; }"
        : "=r"(a) : "l"(p));
    return a;
}
#define SWZ128(o) ((o) ^ (((o) >> 3) & 0x70))

__device__ __forceinline__ void cp16(uint32_t saddr, const void* gptr) {
    asm volatile("cp.async.cg.shared.global [%0], [%1], 16;"
                 :: "r"(saddr), "l"(gptr));
}
#define CP_COMMIT() asm volatile("cp.async.commit_group;" ::: "memory")
#define CP_WAIT0()  asm volatile("cp.async.wait_group 0;" ::: "memory")

__device__ __forceinline__ void ldsm_x4(uint32_t* r, uint32_t addr) {
    asm volatile("ldmatrix.sync.aligned.m8n8.x4.shared.b16 {%0,%1,%2,%3}, [%4];"
                 : "=r"(r[0]), "=r"(r[1]), "=r"(r[2]), "=r"(r[3]) : "r"(addr));
}
__device__ __forceinline__ void ldsm_x4t(uint32_t* r, uint32_t addr) {
    asm volatile("ldmatrix.sync.aligned.m8n8.x4.trans.shared.b16 {%0,%1,%2,%3}, [%4];"
                 : "=r"(r[0]), "=r"(r[1]), "=r"(r[2]), "=r"(r[3]) : "r"(addr));
}
__device__ __forceinline__ void mma_f16(float* c, const uint32_t* a, const uint32_t* b) {
    asm volatile(
        "mma.sync.aligned.m16n8k16.row.col.f32.f16.f16.f32 "
        "{%0,%1,%2,%3}, {%4,%5,%6,%7}, {%8,%9}, {%0,%1,%2,%3};"
        : "+f"(c[0]), "+f"(c[1]), "+f"(c[2]), "+f"(c[3])
        : "r"(a[0]), "r"(a[1]), "r"(a[2]), "r"(a[3]), "r"(b[0]), "r"(b[1]));
}
__device__ __forceinline__ float ex2(float x) {
    float y;
    asm("ex2.approx.ftz.f32 %0, %1;" : "=f"(y) : "f"(x));
    return y;
}
__device__ __forceinline__ void hsplit(float v, __half& h, __half& l) {
    h = __float2half_rn(v);
    l = __float2half_rn(v - __half2float(h));
}
__device__ __forceinline__ void hsplit2(float a, float b, uint32_t& hi, uint32_t& lo) {
    __half2 h = __floats2half2_rn(a, b);
    float2 f = __half22float2(h);
    __half2 l = __floats2half2_rn(a - f.x, b - f.y);
    hi = *reinterpret_cast<uint32_t*>(&h);
    lo = *reinterpret_cast<uint32_t*>(&l);
}

// ---------------- fused prep: token split + coalesced weight transpose ------
#define QSCALE 0.18033688011112042f   // 0.125 * log2(e)

__global__ void prep_all(const float4* __restrict__ tok,
                         const float* __restrict__ wq, const float* __restrict__ wk,
                         const float* __restrict__ wv, const float* __restrict__ wo) {
    __shared__ float tile[32][33];
    const int blk = blockIdx.x;
    const int tid = threadIdx.x;

    if (blk < 4096) {
        int i = blk * 256 + tid;
        float4 v = tok[i];
        uint32_t h01, l01, h23, l23;
        hsplit2(v.x, v.y, h01, l01);
        hsplit2(v.z, v.w, h23, l23);
        uint32_t* H = reinterpret_cast<uint32_t*>(g_tokh);
        uint32_t* L = reinterpret_cast<uint32_t*>(g_tokl);
        H[2 * i] = h01; H[2 * i + 1] = h23;
        L[2 * i] = l01; L[2 * i + 1] = l23;
        return;
    }

    const int wb = blk - 4096;
    if (wb < 3072) {
        const int arr = wb >> 10;
        const int t = wb & 1023;
        const int h = t >> 6;
        const int tt = t & 63;
        const int d0 = (tt >> 1) * 32;
        const int e0 = (tt & 1) * 32;
        const float* src = (arr == 0 ? wq : arr == 1 ? wk : wv) + (size_t)h * DIM * DHEAD;
        __half* dh = (arr == 0 ? g_wqh : arr == 1 ? g_wkh : g_wvh);
        __half* dl = (arr == 0 ? g_wql : g_wkl);   // arr==2 has no lo
        const float scale = (arr == 0) ? QSCALE : 1.0f;

#pragma unroll
        for (int p = 0; p < 4; p++) {
            int lin = p * 256 + tid;
            int r = lin >> 5, c = lin & 31;
            tile[r][c] = src[(size_t)(d0 + r) * DHEAD + e0 + c] * scale;
        }
        __syncthreads();
#pragma unroll
        for (int p = 0; p < 4; p++) {
            int lin = p * 256 + tid;
            int rr = lin >> 5, cc = lin & 31;
            int n = h * 64 + e0 + rr;
            int k = d0 + cc;
            __half hh, ll;
            hsplit(tile[cc][rr], hh, ll);
            dh[(size_t)n * DIM + k] = hh;
            if (arr != 2) dl[(size_t)n * DIM + k] = ll;
        }
    } else {
        const int t2 = wb - 3072;
        const int he0 = (t2 >> 5) * 32;
        const int d0 = (t2 & 31) * 32;
#pragma unroll
        for (int p = 0; p < 4; p++) {
            int lin = p * 256 + tid;
            int r = lin >> 5, c = lin & 31;
            tile[r][c] = wo[(size_t)(he0 + r) * DIM + d0 + c];
        }
        __syncthreads();
#pragma unroll
        for (int p = 0; p < 4; p++) {
            int lin = p * 256 + tid;
            int rr = lin >> 5, cc = lin & 31;
            int n = d0 + rr;
            int k = he0 + cc;
            g_woh[(size_t)n * DIM + k] = __float2half_rn(tile[cc][rr]);
        }
    }
}

// ---------------- GEMMs (HMMA + cp.async 2-stage) -----------------------------
// qkv kernel: z<2 -> x3 split-output (q,k); z==2 -> x1 half-output (v).
#define ST_AL 16384
#define ST_BH 32768
#define ST_BL 40960
#define ST_SZ 49152
#define GS2_TOTAL (2*ST_SZ)

struct QKVArgs {
    const __half* bh[3];
    const __half* bl[2];
    __half* ch[3];
    __half* cl[2];
};

__global__ __launch_bounds__(256, 2) void gemm_qkv(
    const __half* __restrict__ Ah, const __half* __restrict__ Al,
    QKVArgs args) {
    extern __shared__ char smem[];
    const int z = blockIdx.z;
    const bool three = (z != 2);
    const __half* __restrict__ Bh = args.bh[z];
    const __half* __restrict__ Bl = three ? args.bl[z] : nullptr;
    __half* __restrict__ Ch = args.ch[z];
    __half* __restrict__ Cl = three ? args.cl[z] : nullptr;

    const uint32_t sb = smem_u32(smem);
    const int tid = threadIdx.x;
    const int lane = tid & 31;
    const int wid = tid >> 5;
    const int warp_m = wid & 3;
    const int warp_n = wid >> 2;
    const int row0 = blockIdx.y * 128;
    const int col0 = blockIdx.x * 64;

    const uint4* gAh = reinterpret_cast<const uint4*>(Ah + (size_t)row0 * DIM);
    const uint4* gAl = reinterpret_cast<const uint4*>(Al + (size_t)row0 * DIM);
    const uint4* gBh = reinterpret_cast<const uint4*>(Bh + (size_t)col0 * DIM);
    const uint4* gBl = three ? reinterpret_cast<const uint4*>(Bl + (size_t)col0 * DIM)
                             : nullptr;

    const int lrow = tid >> 3, lcol = tid & 7;

    auto load_stage = [&](int cidx, int s) {
        const int k0u = cidx * 8;
        const uint32_t sbase = sb + s * ST_SZ;
#pragma unroll
        for (int r4 = 0; r4 < 4; r4++) {
            int row = lrow + r4 * 32;
            uint32_t off = SWZ128(row * 128 + lcol * 16);
            cp16(sbase + off, gAh + row * 128 + k0u + lcol);
            if (three) cp16(sbase + ST_AL + off, gAl + row * 128 + k0u + lcol);
        }
#pragma unroll
        for (int r4 = 0; r4 < 2; r4++) {
            int row = lrow + r4 * 32;
            uint32_t off = SWZ128(row * 128 + lcol * 16);
            cp16(sbase + ST_BH + off, gBh + row * 128 + k0u + lcol);
            if (three) cp16(sbase + ST_BL + off, gBl + row * 128 + k0u + lcol);
        }
        CP_COMMIT();
    };

    int amask[2], abase[2];
#pragma unroll
    for (int i = 0; i < 2; i++) {
        int r = warp_m * 32 + i * 16 + (lane & 15);
        amask[i] = (r & 7) << 4;
        abase[i] = r * 128 + ((lane >> 4) & 1) * 16;
    }
    const int bRow = ((lane >> 4) & 1) * 8 + (lane & 7);
    const int bHalf = ((lane >> 3) & 1) * 16;

    float acc[2][4][4] = {};

    load_stage(0, 0);
    CP_WAIT0();
    __syncthreads();

    for (int c = 0; c < 16; c++) {
        if (c < 15) load_stage(c + 1, (c + 1) & 1);
        const uint32_t sbase = sb + (c & 1) * ST_SZ;
#pragma unroll
        for (int ks = 0; ks < 4; ks++) {
            uint32_t ah[2][4], al[2][4], bh[4][2], bl[4][2];
#pragma unroll
            for (int i = 0; i < 2; i++) {
                uint32_t offA = (abase[i] + ks * 32) ^ amask[i];
                ldsm_x4(ah[i], sbase + offA);
                if (three) ldsm_x4(al[i], sbase + ST_AL + offA);
            }
#pragma unroll
            for (int jp = 0; jp < 2; jp++) {
                int r = warp_n * 32 + jp * 16 + bRow;
                uint32_t offB = SWZ128(r * 128 + ks * 32 + bHalf);
                ldsm_x4(&bh[2 * jp][0], sbase + ST_BH + offB);
                if (three) ldsm_x4(&bl[2 * jp][0], sbase + ST_BL + offB);
            }
#pragma unroll
            for (int i = 0; i < 2; i++)
#pragma unroll
                for (int j = 0; j < 4; j++)
                    mma_f16(acc[i][j], ah[i], bh[j]);
            if (three) {
#pragma unroll
                for (int i = 0; i < 2; i++)
#pragma unroll
                    for (int j = 0; j < 4; j++)
                        mma_f16(acc[i][j], ah[i], bl[j]);
#pragma unroll
                for (int i = 0; i < 2; i++)
#pragma unroll
                    for (int j = 0; j < 4; j++)
                        mma_f16(acc[i][j], al[i], bh[j]);
            }
        }
        if (c < 15) {
            CP_WAIT0();
            __syncthreads();
        }
    }

    const int fr = lane >> 2, fc = (lane & 3) * 2;
#pragma unroll
    for (int i = 0; i < 2; i++) {
        int rbase = row0 + warp_m * 32 + i * 16 + fr;
#pragma unroll
        for (int j = 0; j < 4; j++) {
            int col = col0 + warp_n * 32 + j * 8 + fc;
            if (three) {
                uint32_t h01, l01;
                hsplit2(acc[i][j][0], acc[i][j][1], h01, l01);
                *reinterpret_cast<uint32_t*>(&Ch[(size_t)rbase * DIM + col]) = h01;
                *reinterpret_cast<uint32_t*>(&Cl[(size_t)rbase * DIM + col]) = l01;
                hsplit2(acc[i][j][2], acc[i][j][3], h01, l01);
                *reinterpret_cast<uint32_t*>(&Ch[(size_t)(rbase + 8) * DIM + col]) = h01;
                *reinterpret_cast<uint32_t*>(&Cl[(size_t)(rbase + 8) * DIM + col]) = l01;
            } else {
                __half2 t = __floats2half2_rn(acc[i][j][0], acc[i][j][1]);
                *reinterpret_cast<__half2*>(&Ch[(size_t)rbase * DIM + col]) = t;
                t = __floats2half2_rn(acc[i][j][2], acc[i][j][3]);
                *reinterpret_cast<__half2*>(&Ch[(size_t)(rbase + 8) * DIM + col]) = t;
            }
        }
    }
}

// wo x1: C[fp32] = Ah * Bh^T. stage: AH 16K | BH 8K = 24K; 2 stages = 48K.
#define W1_BH 16384
#define W1_SZ 24576
#define GW1_TOTAL (2*W1_SZ)

__global__ __launch_bounds__(256, 2) void gemm_wo_x1(
    const __half* __restrict__ Ah, const __half* __restrict__ Bh,
    float* __restrict__ C) {
    extern __shared__ char smem[];
    const uint32_t sb = smem_u32(smem);
    const int tid = threadIdx.x;
    const int lane = tid & 31;
    const int wid = tid >> 5;
    const int warp_m = wid & 3;
    const int warp_n = wid >> 2;
    const int row0 = blockIdx.y * 128;
    const int col0 = blockIdx.x * 64;

    const uint4* gA = reinterpret_cast<const uint4*>(Ah + (size_t)row0 * DIM);
    const uint4* gB = reinterpret_cast<const uint4*>(Bh + (size_t)col0 * DIM);

    const int lrow = tid >> 3, lcol = tid & 7;

    auto load_stage = [&](int cidx, int s) {
        const int k0u = cidx * 8;
        const uint32_t sbase = sb + s * W1_SZ;
#pragma unroll
        for (int r4 = 0; r4 < 4; r4++) {
            int row = lrow + r4 * 32;
            uint32_t off = SWZ128(row * 128 + lcol * 16);
            cp16(sbase + off, gA + row * 128 + k0u + lcol);
        }
#pragma unroll
        for (int r4 = 0; r4 < 2; r4++) {
            int row = lrow + r4 * 32;
            uint32_t off = SWZ128(row * 128 + lcol * 16);
            cp16(sbase + W1_BH + off, gB + row * 128 + k0u + lcol);
        }
        CP_COMMIT();
    };

    int amask[2], abase[2];
#pragma unroll
    for (int i = 0; i < 2; i++) {
        int r = warp_m * 32 + i * 16 + (lane & 15);
        amask[i] = (r & 7) << 4;
        abase[i] = r * 128 + ((lane >> 4) & 1) * 16;
    }
    const int bRow = ((lane >> 4) & 1) * 8 + (lane & 7);
    const int bHalf = ((lane >> 3) & 1) * 16;

    float acc[2][4][4] = {};

    load_stage(0, 0);
    CP_WAIT0();
    __syncthreads();

    for (int c = 0; c < 16; c++) {
        if (c < 15) load_stage(c + 1, (c + 1) & 1);
        const uint32_t sbase = sb + (c & 1) * W1_SZ;
#pragma unroll
        for (int ks = 0; ks < 4; ks++) {
            uint32_t ah[2][4], bh[4][2];
#pragma unroll
            for (int i = 0; i < 2; i++) {
                uint32_t offA = (abase[i] + ks * 32) ^ amask[i];
                ldsm_x4(ah[i], sbase + offA);
            }
#pragma unroll
            for (int jp = 0; jp < 2; jp++) {
                int r = warp_n * 32 + jp * 16 + bRow;
                uint32_t offB = SWZ128(r * 128 + ks * 32 + bHalf);
                ldsm_x4(&bh[2 * jp][0], sbase + W1_BH + offB);
            }
#pragma unroll
            for (int i = 0; i < 2; i++)
#pragma unroll
                for (int j = 0; j < 4; j++)
                    mma_f16(acc[i][j], ah[i], bh[j]);
        }
        if (c < 15) {
            CP_WAIT0();
            __syncthreads();
        }
    }

    const int fr = lane >> 2, fc = (lane & 3) * 2;
#pragma unroll
    for (int i = 0; i < 2; i++) {
        int rbase = row0 + warp_m * 32 + i * 16 + fr;
#pragma unroll
        for (int j = 0; j < 4; j++) {
            int col = col0 + warp_n * 32 + j * 8 + fc;
            *reinterpret_cast<float2*>(&C[(size_t)rbase * DIM + col]) =
                make_float2(acc[i][j][0], acc[i][j][1]);
            *reinterpret_cast<float2*>(&C[(size_t)(rbase + 8) * DIM + col]) =
                make_float2(acc[i][j][2], acc[i][j][3]);
        }
    }
}

// ---------------- flash attention (fp16; QK x3 exp2 domain, PV x1) -----------
#define FA_QL 16384
#define FA_KV0 32768
#define FA_KVS 24576
#define FA_KL_O 8192
#define FA_VH_O 16384
#define FA_TOTAL (32768 + 2*24576)   // 81920

__global__ __launch_bounds__(256, 2) void flash_attn_mma(
    const __half* __restrict__ Qh, const __half* __restrict__ Ql,
    const __half* __restrict__ Kh, const __half* __restrict__ Kl,
    const __half* __restrict__ Vh, __half* __restrict__ O) {
    extern __shared__ char smem[];
    const uint32_t sb = smem_u32(smem);
    const int tid = threadIdx.x, lane = tid & 31, wid = tid >> 5;
    const int qt = blockIdx.x, bhid = blockIdx.y;
    const int b = bhid >> 4, h = bhid & 15;
    const size_t base = ((size_t)(b * SEQ) * HEADS + h) * DHEAD;
    const uint4* Qhp = reinterpret_cast<const uint4*>(Qh + base);
    const uint4* Qlp = reinterpret_cast<const uint4*>(Ql + base);
    const uint4* Khp = reinterpret_cast<const uint4*>(Kh + base);
    const uint4* Klp = reinterpret_cast<const uint4*>(Kl + base);
    const uint4* Vhp = reinterpret_cast<const uint4*>(Vh + base);

    const int lrw = tid >> 3, lcl = tid & 7;

    auto load_kv = [&](int jt, int s) {
        const uint32_t kvb = sb + FA_KV0 + s * FA_KVS;
#pragma unroll
        for (int r4 = 0; r4 < 2; r4++) {
            int row = lrw + r4 * 32;
            uint32_t off = SWZ128(row * 128 + lcl * 16);
            int g = (jt * 64 + row) * 128 + lcl;
            cp16(kvb + off, Khp + g);
            cp16(kvb + FA_KL_O + off, Klp + g);
            cp16(kvb + FA_VH_O + off, Vhp + g);
        }
        CP_COMMIT();
    };

    load_kv(0, 0);
#pragma unroll
    for (int r4 = 0; r4 < 4; r4++) {
        int row = lrw + r4 * 32;
        uint32_t off = SWZ128(row * 128 + lcl * 16);
        int g = (qt * 128 + row) * 128 + lcl;
        *reinterpret_cast<uint4*>(smem + off) = Qhp[g];
        *reinterpret_cast<uint4*>(smem + FA_QL + off) = Qlp[g];
    }

    float m0 = -1e30f, m1 = -1e30f, l0 = 0.f, l1 = 0.f;
    float o[8][4] = {};
    const int fr = lane >> 2, fc = (lane & 3) * 2;
    const int qrow = wid * 16;
    const int aRow = lane & 15, aCol = (lane >> 4) * 16;
    const int kRow = ((lane >> 4) & 1) * 8 + (lane & 7);
    const int kHalf = ((lane >> 3) & 1) * 16;
    const int vRow = lane & 15;
    const int vColOff = ((lane >> 4) & 1) * 8;

    CP_WAIT0();
    __syncthreads();

    for (int jt = 0; jt < SEQ / 64; jt++) {
        const uint32_t kvb = sb + FA_KV0 + (jt & 1) * FA_KVS;
        if (jt + 1 < SEQ / 64) load_kv(jt + 1, (jt + 1) & 1);

        // ---- S = Q K^T (fp16 x3), exp2 domain ----
        float s[8][4] = {};
#pragma unroll
        for (int ks = 0; ks < 4; ks++) {
            uint32_t ah[4], al[4];
            uint32_t offA = SWZ128((qrow + aRow) * 128 + ks * 32 + aCol);
            ldsm_x4(ah, sb + offA);
            ldsm_x4(al, sb + FA_QL + offA);
#pragma unroll
            for (int jp = 0; jp < 2; jp++) {
                uint32_t kh4[2][4], kl4[2][4];
#pragma unroll
                for (int u = 0; u < 2; u++) {
                    int jj = jp * 2 + u;
                    uint32_t offB = SWZ128((jj * 16 + kRow) * 128 + ks * 32 + kHalf);
                    ldsm_x4(kh4[u], kvb + offB);
                    ldsm_x4(kl4[u], kvb + FA_KL_O + offB);
                }
#pragma unroll
                for (int u = 0; u < 2; u++) {
                    int jj = jp * 2 + u;
                    mma_f16(s[2 * jj], ah, kh4[u]);
                    mma_f16(s[2 * jj + 1], ah, kh4[u] + 2);
                }
#pragma unroll
                for (int u = 0; u < 2; u++) {
                    int jj = jp * 2 + u;
                    mma_f16(s[2 * jj], ah, kl4[u]);
                    mma_f16(s[2 * jj + 1], ah, kl4[u] + 2);
                }
#pragma unroll
                for (int u = 0; u < 2; u++) {
                    int jj = jp * 2 + u;
                    mma_f16(s[2 * jj], al, kh4[u]);
                    mma_f16(s[2 * jj + 1], al, kh4[u] + 2);
                }
            }
        }

        // ---- warp-local row max ----
        float rm0 = s[0][0], rm1 = s[0][2];
#pragma unroll
        for (int j = 0; j < 8; j++) {
            rm0 = fmaxf(rm0, fmaxf(s[j][0], s[j][1]));
            rm1 = fmaxf(rm1, fmaxf(s[j][2], s[j][3]));
        }
        rm0 = fmaxf(rm0, __shfl_xor_sync(0xffffffffu, rm0, 1));
        rm0 = fmaxf(rm0, __shfl_xor_sync(0xffffffffu, rm0, 2));
        rm1 = fmaxf(rm1, __shfl_xor_sync(0xffffffffu, rm1, 1));
        rm1 = fmaxf(rm1, __shfl_xor_sync(0xffffffffu, rm1, 2));
        float mn0 = fmaxf(m0, rm0), mn1 = fmaxf(m1, rm1);
        float a0 = ex2(m0 - mn0), a1 = ex2(m1 - mn1);
        m0 = mn0; m1 = mn1;

#pragma unroll
        for (int j = 0; j < 8; j++) {
            o[j][0] *= a0; o[j][1] *= a0;
            o[j][2] *= a1; o[j][3] *= a1;
        }

        // ---- PV x1 with fused exp2/pack ----
        float rs0 = 0.f, rs1 = 0.f;
#pragma unroll
        for (int kt = 0; kt < 4; kt++) {
            uint32_t pA[4];
#pragma unroll
            for (int u = 0; u < 2; u++) {
                int j = 2 * kt + u;
                float p0 = ex2(s[j][0] - mn0);
                float p1 = ex2(s[j][1] - mn0);
                float p2 = ex2(s[j][2] - mn1);
                float p3 = ex2(s[j][3] - mn1);
                rs0 += p0 + p1; rs1 += p2 + p3;
                __half2 t01 = __floats2half2_rn(p0, p1);
                __half2 t23 = __floats2half2_rn(p2, p3);
                pA[2 * u] = *reinterpret_cast<uint32_t*>(&t01);
                pA[2 * u + 1] = *reinterpret_cast<uint32_t*>(&t23);
            }
#pragma unroll
            for (int jj = 0; jj < 4; jj++) {
                uint32_t vh4[4];
                uint32_t offV = SWZ128((kt * 16 + vRow) * 128 + (jj * 16 + vColOff) * 2);
                ldsm_x4t(vh4, kvb + FA_VH_O + offV);
                mma_f16(o[2 * jj], pA, vh4);
                mma_f16(o[2 * jj + 1], pA, vh4 + 2);
            }
        }
        rs0 += __shfl_xor_sync(0xffffffffu, rs0, 1);
        rs0 += __shfl_xor_sync(0xffffffffu, rs0, 2);
        rs1 += __shfl_xor_sync(0xffffffffu, rs1, 1);
        rs1 += __shfl_xor_sync(0xffffffffu, rs1, 2);
        l0 = l0 * a0 + rs0;
        l1 = l1 * a1 + rs1;

        if (jt + 1 < SEQ / 64) CP_WAIT0();
        __syncthreads();
    }

    // ---- epilogue: normalize, round to fp16, store [b,n,h,e] ----
    float inv0 = 1.f / l0, inv1 = 1.f / l1;
    const int r0g = qt * 128 + qrow + fr;
#pragma unroll
    for (int j = 0; j < 8; j++) {
        int col = j * 8 + fc;
        __half2 t = __floats2half2_rn(o[j][0] * inv0, o[j][1] * inv0);
        *reinterpret_cast<__half2*>(O + base + (size_t)r0g * 1024 + col) = t;
        t = __floats2half2_rn(o[j][2] * inv1, o[j][3] * inv1);
        *reinterpret_cast<__half2*>(O + base + (size_t)(r0g + 8) * 1024 + col) = t;
    }
}

// ---------------- launch ------------------------------------------------------
extern "C" void kernel_launch(void* const* d_in, const int* in_sizes, int n_in,
                              void* d_out, int out_size) {
    const float* tokens = (const float*)d_in[0];
    const float* wq = (const float*)d_in[1];
    const float* wk = (const float*)d_in[2];
    const float* wv = (const float*)d_in[3];
    const float* wo = (const float*)d_in[4];
    float* out = (float*)d_out;

    __half *tokh, *tokl, *qh, *ql, *kh, *kl, *v, *agg;
    __half *wqh, *wql, *wkh, *wkl, *wvh, *woh;
    cudaGetSymbolAddress((void**)&tokh, g_tokh);
    cudaGetSymbolAddress((void**)&tokl, g_tokl);
    cudaGetSymbolAddress((void**)&qh, g_qh);
    cudaGetSymbolAddress((void**)&ql, g_ql);
    cudaGetSymbolAddress((void**)&kh, g_kh);
    cudaGetSymbolAddress((void**)&kl, g_kl);
    cudaGetSymbolAddress((void**)&v, g_v);
    cudaGetSymbolAddress((void**)&agg, g_agg);
    cudaGetSymbolAddress((void**)&wqh, g_wqh);
    cudaGetSymbolAddress((void**)&wql, g_wql);
    cudaGetSymbolAddress((void**)&wkh, g_wkh);
    cudaGetSymbolAddress((void**)&wkl, g_wkl);
    cudaGetSymbolAddress((void**)&wvh, g_wvh);
    cudaGetSymbolAddress((void**)&woh, g_woh);

    prep_all<<<8192, 256>>>((const float4*)tokens, wq, wk, wv, wo);

    cudaFuncSetAttribute(gemm_qkv, cudaFuncAttributeMaxDynamicSharedMemorySize,
                         GS2_TOTAL);
    cudaFuncSetAttribute(gemm_wo_x1, cudaFuncAttributeMaxDynamicSharedMemorySize,
                         GW1_TOTAL);

    QKVArgs args;
    args.bh[0] = wqh; args.bl[0] = wql; args.ch[0] = qh; args.cl[0] = ql;
    args.bh[1] = wkh; args.bl[1] = wkl; args.ch[1] = kh; args.cl[1] = kl;
    args.bh[2] = wvh; args.ch[2] = v;

    dim3 gqkv(DIM / 64, BS / 128, 3);
    gemm_qkv<<<gqkv, 256, GS2_TOTAL>>>(tokh, tokl, args);

    cudaFuncSetAttribute(flash_attn_mma,
                         cudaFuncAttributeMaxDynamicSharedMemorySize, FA_TOTAL);
    flash_attn_mma<<<dim3(SEQ / 128, BATCH * HEADS), 256, FA_TOTAL>>>(
        qh, ql, kh, kl, v, agg);

    dim3 gp(DIM / 64, BS / 128);
    gemm_wo_x1<<<gp, 256, GW1_TOTAL>>>(agg, woh, out);
}